// round 15
// baseline (speedup 1.0000x reference)
#include <cuda_runtime.h>
#include <cuda_fp16.h>

#define NN   100000
#define NE   1600000
#define INC  26
#define HID  128
#define OUTC 64
#define BN_EPS 1e-5f
#define OUT_ELEMS (NN * OUTC)
#define CSR_CAP (NE + 4 * NN)

// ---------------- device scratch ----------------
__device__ float  g_x[NN * HID];    // raw (pre-BN) layer outputs, fp32
__device__ __half g_xh[NN * HID];   // pre-scaled activations, fp16 (gather input)
__device__ __half g_h16[NN * 32];   // layer-0 messages: half(h * norm_src), padded to 32ch
__device__ float  g_agg[NN * HID];  // gather accumulator (layer0 uses NN*32 padded)
__device__ float  g_norm_src[NN];
__device__ float  g_norm_dst[NN];
__device__ int    g_deg_out_i[NN];
__device__ int    g_deg_in_i[NN];
__device__ int    g_rowptr[NN];
__device__ int    g_cursor[NN];
__device__ int    g_csr_src[CSR_CAP];
__device__ int    g_total;
__device__ float  g_sum[3 * HID];   // BN stats, one slot per BN layer
__device__ float  g_sumsq[3 * HID];

__constant__ float c_wtable[26] = {
    0.7f,0.9f,0.7f,0.9f,0.3f,0.7f,0.3f,0.9f,0.3f,0.3f,0.9f,0.7f,0.1f,
    0.9f,0.5f,0.9f,0.5f,0.5f,0.1f,0.3f,0.7f,0.9f,0.9f,0.9f,0.9f,0.9f};

__device__ __forceinline__ void tf32_split(float v, unsigned int& hi, unsigned int& lo) {
    asm("cvt.rna.tf32.f32 %0, %1;" : "=r"(hi) : "f"(v));
    float rem = v - __uint_as_float(hi);
    asm("cvt.rna.tf32.f32 %0, %1;" : "=r"(lo) : "f"(rem));
}

// ---------------- prep kernels ----------------
__global__ void k_zero_deg() {
    int n = blockIdx.x * blockDim.x + threadIdx.x;
    if (n < NN) { g_deg_out_i[n] = 0; g_deg_in_i[n] = 0; }
    if (n < 3 * HID) { g_sum[n] = 0.f; g_sumsq[n] = 0.f; }
    if (n == 0) g_total = 0;
}

// 4 edges per thread, int4 index loads
__global__ void k_degrees(const int* __restrict__ src, const int* __restrict__ dst) {
    int t = blockIdx.x * blockDim.x + threadIdx.x;
    if (t >= NE / 4) return;
    int4 s = ((const int4*)src)[t];
    int4 d = ((const int4*)dst)[t];
    atomicAdd(&g_deg_out_i[s.x], 1);
    atomicAdd(&g_deg_out_i[s.y], 1);
    atomicAdd(&g_deg_out_i[s.z], 1);
    atomicAdd(&g_deg_out_i[s.w], 1);
    atomicAdd(&g_deg_in_i[d.x], 1);
    atomicAdd(&g_deg_in_i[d.y], 1);
    atomicAdd(&g_deg_in_i[d.z], 1);
    atomicAdd(&g_deg_in_i[d.w], 1);
}

// merged: argmax weight + degree norms + fp16 layer-0 messages + segment alloc
__global__ void k_nodeprep_alloc(const float* __restrict__ h, float* __restrict__ out) {
    int n = blockIdx.x * blockDim.x + threadIdx.x;
    int lane = threadIdx.x & 31;

    int dpad = 0, deg_in = 0;
    if (n < NN) {
        deg_in = g_deg_in_i[n];
        dpad = (deg_in + 3) & ~3;
    }
    int incl = dpad;
#pragma unroll
    for (int o = 1; o < 32; o <<= 1) {
        int t = __shfl_up_sync(0xffffffff, incl, o);
        if (lane >= o) incl += t;
    }
    int wtotal = __shfl_sync(0xffffffff, incl, 31);
    int base = 0;
    if (lane == 0) base = atomicAdd(&g_total, wtotal);
    base = __shfl_sync(0xffffffff, base, 0);
    if (n >= NN) return;
    int pos = base + incl - dpad;
    g_rowptr[n] = pos;
    g_cursor[n] = pos;

    const float* hr = h + (size_t)n * INC;
    float hv[INC];
    float best = -1e30f;
    int bi = 0;
#pragma unroll
    for (int c = 0; c < INC; c++) {
        float v = hr[c];
        hv[c] = v;
        if (v > best) { best = v; bi = c; }
    }
    out[OUT_ELEMS + n] = c_wtable[bi];
    float ns = rsqrtf(fmaxf((float)g_deg_out_i[n], 1.f));
    g_norm_src[n] = ns;
    g_norm_dst[n] = rsqrtf(fmaxf((float)deg_in, 1.f));
    unsigned int* dsth = (unsigned int*)g_h16 + (size_t)n * 16;
#pragma unroll
    for (int j = 0; j < 13; j++) {
        __half2 p = __floats2half2_rn(hv[2 * j] * ns, hv[2 * j + 1] * ns);
        dsth[j] = *(unsigned int*)&p;
    }
    dsth[13] = 0; dsth[14] = 0; dsth[15] = 0;
}

// 4 edges per thread, int4 index loads
__global__ void k_fill(const int* __restrict__ src, const int* __restrict__ dst) {
    int t = blockIdx.x * blockDim.x + threadIdx.x;
    if (t >= NE / 4) return;
    int4 s = ((const int4*)src)[t];
    int4 d = ((const int4*)dst)[t];
    g_csr_src[atomicAdd(&g_cursor[d.x], 1)] = s.x;
    g_csr_src[atomicAdd(&g_cursor[d.y], 1)] = s.y;
    g_csr_src[atomicAdd(&g_cursor[d.z], 1)] = s.z;
    g_csr_src[atomicAdd(&g_cursor[d.w], 1)] = s.w;
}

// ---------------- layer-0 gather: fp16 packed rows, half-warp per edge ----------------
__global__ void k_gather26() {
    int gid = blockIdx.x * blockDim.x + threadIdx.x;
    int n = gid >> 5;
    int lane = gid & 31;
    if (n >= NN) return;
    int sub = lane & 15;
    int w = lane >> 4;
    int start = g_rowptr[n];
    int cnt = g_deg_in_i[n];
    const int* cs = g_csr_src + start;
    const unsigned int* xh = (const unsigned int*)g_h16;
    float2 acc = make_float2(0.f, 0.f);
    int i = 0;
    for (; i + 4 <= cnt; i += 4) {
        int sA = cs[i + w];
        int sB = cs[i + 2 + w];
        unsigned int pA = __ldg(xh + (size_t)sA * 16 + sub);
        unsigned int pB = __ldg(xh + (size_t)sB * 16 + sub);
        float2 a = __half22float2(*(__half2*)&pA);
        float2 b = __half22float2(*(__half2*)&pB);
        acc.x += a.x + b.x;
        acc.y += a.y + b.y;
    }
    for (; i < cnt; i += 2) {
        int e = i + w;
        if (e < cnt) {
            int s = cs[e];
            unsigned int p = __ldg(xh + (size_t)s * 16 + sub);
            float2 a = __half22float2(*(__half2*)&p);
            acc.x += a.x;
            acc.y += a.y;
        }
    }
    acc.x += __shfl_xor_sync(0xffffffff, acc.x, 16);
    acc.y += __shfl_xor_sync(0xffffffff, acc.y, 16);
    if (w == 0) {
        ((float2*)(g_agg + (size_t)n * 32))[sub] = acc;
    }
}

// pre-scale: computes BN scale/shift from stats slot, then
// g_xh <- half(relu(bn(g_x)) * norm_src[row])
__global__ void k_prescale(const float* __restrict__ g, const float* __restrict__ bt,
                           int slot) {
    __shared__ float scs[HID], shs[HID];
    int tid = threadIdx.x;
    if (tid < HID) {
        float inv_n = 1.f / (float)NN;
        float mu = g_sum[slot * HID + tid] * inv_n;
        float var = g_sumsq[slot * HID + tid] * inv_n - mu * mu;
        float sc = g[tid] * rsqrtf(var + BN_EPS);
        scs[tid] = sc;
        shs[tid] = bt[tid] - mu * sc;
    }
    __syncthreads();
    int i = blockIdx.x * blockDim.x + threadIdx.x;
    if (i >= NN * (HID / 4)) return;
    int lane = i & 31;
    int row = i >> 5;
    float4 sc = *(const float4*)(scs + lane * 4);
    float4 sh = *(const float4*)(shs + lane * 4);
    float ns = g_norm_src[row];
    float4 v = ((const float4*)g_x)[i];
    float2 lo = make_float2(fmaxf(fmaf(v.x, sc.x, sh.x), 0.f) * ns,
                            fmaxf(fmaf(v.y, sc.y, sh.y), 0.f) * ns);
    float2 hi = make_float2(fmaxf(fmaf(v.z, sc.z, sh.z), 0.f) * ns,
                            fmaxf(fmaf(v.w, sc.w, sh.w), 0.f) * ns);
    __half2 h0 = __float22half2_rn(lo);
    __half2 h1 = __float22half2_rn(hi);
    uint2 packed;
    packed.x = *(unsigned int*)&h0;
    packed.y = *(unsigned int*)&h1;
    ((uint2*)g_xh)[i] = packed;
}

// gather: half-warp per edge, LDG.128 row loads (16 lanes x uint4 = 256B row)
// half-warp w handles edge block [i+8w, i+8w+8); cross-half-warp shfl reduce at end
__global__ void k_gather128() {
    int gid = blockIdx.x * blockDim.x + threadIdx.x;
    int n = gid >> 5;
    int lane = gid & 31;
    if (n >= NN) return;
    int sub = lane & 15;   // 16B chunk within row: channels [sub*8, sub*8+8)
    int w = lane >> 4;
    const int* cs = g_csr_src + g_rowptr[n];
    int cnt = g_deg_in_i[n];
    const uint4* xh = (const uint4*)g_xh;  // row = 16 uint4
    float4 a0 = make_float4(0.f, 0.f, 0.f, 0.f);
    float4 a1 = make_float4(0.f, 0.f, 0.f, 0.f);
    float2 q;
#define ACCU4(P) \
    q = __half22float2(*(__half2*)&P.x); a0.x += q.x; a0.y += q.y; \
    q = __half22float2(*(__half2*)&P.y); a0.z += q.x; a0.w += q.y; \
    q = __half22float2(*(__half2*)&P.z); a1.x += q.x; a1.y += q.y; \
    q = __half22float2(*(__half2*)&P.w); a1.z += q.x; a1.w += q.y;
    int i = 0;
    for (; i + 16 <= cnt; i += 16) {
        int4 ia = *(const int4*)(cs + i + 8 * w);
        int4 ib = *(const int4*)(cs + i + 8 * w + 4);
        uint4 p0 = __ldg(xh + (size_t)ia.x * 16 + sub);
        uint4 p1 = __ldg(xh + (size_t)ia.y * 16 + sub);
        uint4 p2 = __ldg(xh + (size_t)ia.z * 16 + sub);
        uint4 p3 = __ldg(xh + (size_t)ia.w * 16 + sub);
        uint4 p4 = __ldg(xh + (size_t)ib.x * 16 + sub);
        uint4 p5 = __ldg(xh + (size_t)ib.y * 16 + sub);
        uint4 p6 = __ldg(xh + (size_t)ib.z * 16 + sub);
        uint4 p7 = __ldg(xh + (size_t)ib.w * 16 + sub);
        ACCU4(p0) ACCU4(p1) ACCU4(p2) ACCU4(p3)
        ACCU4(p4) ACCU4(p5) ACCU4(p6) ACCU4(p7)
    }
    for (; i + 2 <= cnt; i += 2) {
        int s = cs[i + w];
        uint4 p = __ldg(xh + (size_t)s * 16 + sub);
        ACCU4(p)
    }
    if (i < cnt && w == 0) {
        int s = cs[i];
        uint4 p = __ldg(xh + (size_t)s * 16 + sub);
        ACCU4(p)
    }
#undef ACCU4
    a0.x += __shfl_xor_sync(0xffffffff, a0.x, 16);
    a0.y += __shfl_xor_sync(0xffffffff, a0.y, 16);
    a0.z += __shfl_xor_sync(0xffffffff, a0.z, 16);
    a0.w += __shfl_xor_sync(0xffffffff, a0.w, 16);
    a1.x += __shfl_xor_sync(0xffffffff, a1.x, 16);
    a1.y += __shfl_xor_sync(0xffffffff, a1.y, 16);
    a1.z += __shfl_xor_sync(0xffffffff, a1.z, 16);
    a1.w += __shfl_xor_sync(0xffffffff, a1.w, 16);
    if (w == 0) {
        float4* dst = (float4*)(g_agg + (size_t)n * HID + sub * 8);
        dst[0] = a0;
        dst[1] = a1;
    }
}

// ============ GEMMs: 3xTF32 with fragment-layout W ============

// ---- layer-0 GEMM: K=32 (4 ks), 128 cols (16 groups) ----
#define L0_WFRAG_F4 (4 * 16 * 32)
#define L0_LDX 132
#define L0_XHI (L0_WFRAG_F4 * 4)
#define L0_XLO (L0_WFRAG_F4 * 4 + 64 * L0_LDX)
#define L0_SMEM ((L0_WFRAG_F4 * 4 + 2 * 64 * L0_LDX) * 4)
#define L0_GRID 148
__global__ void __launch_bounds__(256, 1) k_gemm_l0_tf32(const float* __restrict__ W,
                                                         const float* __restrict__ b) {
    extern __shared__ float sm[];
    float4* Wfrag = (float4*)sm;
    float* xhi = sm + L0_XHI;
    float* xlo = sm + L0_XLO;
    int tid = threadIdx.x, lane = tid & 31, warp = tid >> 5;
    int g = lane >> 2, tg = lane & 3;

    for (int i = tid; i < L0_WFRAG_F4; i += 256) {
        int li = i & 31, cg = (i >> 5) & 15, ks = i >> 9;
        int c = cg * 8 + (li >> 2);
        int k = ks * 8 + (li & 3);
        float v0 = (k < INC) ? W[k * HID + c] : 0.f;
        float v1 = (k + 4 < INC) ? W[(k + 4) * HID + c] : 0.f;
        unsigned int h0, l0, h1, l1;
        tf32_split(v0, h0, l0);
        tf32_split(v1, h1, l1);
        float4 f;
        f.x = __uint_as_float(h0); f.y = __uint_as_float(h1);
        f.z = __uint_as_float(l0); f.w = __uint_as_float(l1);
        Wfrag[i] = f;
    }

    int wrow = (warp & 3) * 16;
    int wcol = (warp >> 2) * 64;
    int ntbase = (warp >> 2) * 8;
    float bcx[8], bcy[8];
#pragma unroll
    for (int nt = 0; nt < 8; nt++) {
        int c = wcol + nt * 8 + 2 * tg;
        bcx[nt] = __ldg(&b[c]);
        bcy[nt] = __ldg(&b[c + 1]);
    }
    float scol[16], qcol[16];
#pragma unroll
    for (int t = 0; t < 16; t++) { scol[t] = 0.f; qcol[t] = 0.f; }

    for (int rb = blockIdx.x * 64; rb < NN; rb += L0_GRID * 64) {
        __syncthreads();
        for (int i = tid; i < 64 * 8; i += 256) {
            int row = i >> 3, t4 = i & 7;
            int gr = rb + row;
            float4 v = (gr < NN) ? ((const float4*)g_agg)[(size_t)gr * 8 + t4]
                                 : make_float4(0.f, 0.f, 0.f, 0.f);
            uint4 hi, lo;
            tf32_split(v.x, hi.x, lo.x);
            tf32_split(v.y, hi.y, lo.y);
            tf32_split(v.z, hi.z, lo.z);
            tf32_split(v.w, hi.w, lo.w);
            *(uint4*)(xhi + row * L0_LDX + t4 * 4) = hi;
            *(uint4*)(xlo + row * L0_LDX + t4 * 4) = lo;
        }
        __syncthreads();

        float d[8][4];
#pragma unroll
        for (int nt = 0; nt < 8; nt++) { d[nt][0]=0.f; d[nt][1]=0.f; d[nt][2]=0.f; d[nt][3]=0.f; }

#pragma unroll
        for (int ks = 0; ks < 4; ks++) {
            int k0 = ks * 8;
            unsigned int ah0 = __float_as_uint(xhi[(wrow + g) * L0_LDX + k0 + tg]);
            unsigned int ah1 = __float_as_uint(xhi[(wrow + g + 8) * L0_LDX + k0 + tg]);
            unsigned int ah2 = __float_as_uint(xhi[(wrow + g) * L0_LDX + k0 + tg + 4]);
            unsigned int ah3 = __float_as_uint(xhi[(wrow + g + 8) * L0_LDX + k0 + tg + 4]);
            unsigned int al0 = __float_as_uint(xlo[(wrow + g) * L0_LDX + k0 + tg]);
            unsigned int al1 = __float_as_uint(xlo[(wrow + g + 8) * L0_LDX + k0 + tg]);
            unsigned int al2 = __float_as_uint(xlo[(wrow + g) * L0_LDX + k0 + tg + 4]);
            unsigned int al3 = __float_as_uint(xlo[(wrow + g + 8) * L0_LDX + k0 + tg + 4]);
            const float4* wf = Wfrag + (ks * 16 + ntbase) * 32 + lane;
#pragma unroll
            for (int nt = 0; nt < 8; nt++) {
                float4 bf = wf[nt * 32];
                unsigned int bh0 = __float_as_uint(bf.x);
                unsigned int bh1 = __float_as_uint(bf.y);
                unsigned int bl0 = __float_as_uint(bf.z);
                unsigned int bl1 = __float_as_uint(bf.w);
#define MMA(A0,A1,A2,A3,B0,B1) \
                asm volatile( \
                    "mma.sync.aligned.m16n8k8.row.col.f32.tf32.tf32.f32 " \
                    "{%0,%1,%2,%3}, {%4,%5,%6,%7}, {%8,%9}, {%0,%1,%2,%3};" \
                    : "+f"(d[nt][0]), "+f"(d[nt][1]), "+f"(d[nt][2]), "+f"(d[nt][3]) \
                    : "r"(A0), "r"(A1), "r"(A2), "r"(A3), "r"(B0), "r"(B1));
                MMA(ah0, ah1, ah2, ah3, bh0, bh1)
                MMA(ah0, ah1, ah2, ah3, bl0, bl1)
                MMA(al0, al1, al2, al3, bh0, bh1)
#undef MMA
            }
        }

        int r0 = rb + wrow + g;
        int r1 = r0 + 8;
        bool v0 = r0 < NN, v1 = r1 < NN;
        float nd0 = v0 ? g_norm_dst[r0] : 0.f;
        float nd1 = v1 ? g_norm_dst[r1] : 0.f;
#pragma unroll
        for (int nt = 0; nt < 8; nt++) {
            int c = wcol + nt * 8 + 2 * tg;
            if (v0) {
                float yx = d[nt][0] * nd0 + bcx[nt];
                float yy = d[nt][1] * nd0 + bcy[nt];
                *(float2*)(g_x + (size_t)r0 * HID + c) = make_float2(yx, yy);
                scol[nt * 2] += yx;     qcol[nt * 2]     = fmaf(yx, yx, qcol[nt * 2]);
                scol[nt * 2 + 1] += yy; qcol[nt * 2 + 1] = fmaf(yy, yy, qcol[nt * 2 + 1]);
            }
            if (v1) {
                float yx = d[nt][2] * nd1 + bcx[nt];
                float yy = d[nt][3] * nd1 + bcy[nt];
                *(float2*)(g_x + (size_t)r1 * HID + c) = make_float2(yx, yy);
                scol[nt * 2] += yx;     qcol[nt * 2]     = fmaf(yx, yx, qcol[nt * 2]);
                scol[nt * 2 + 1] += yy; qcol[nt * 2 + 1] = fmaf(yy, yy, qcol[nt * 2 + 1]);
            }
        }
    }

#pragma unroll
    for (int t = 0; t < 16; t++) {
        scol[t] += __shfl_xor_sync(0xffffffff, scol[t], 4);
        scol[t] += __shfl_xor_sync(0xffffffff, scol[t], 8);
        scol[t] += __shfl_xor_sync(0xffffffff, scol[t], 16);
        qcol[t] += __shfl_xor_sync(0xffffffff, qcol[t], 4);
        qcol[t] += __shfl_xor_sync(0xffffffff, qcol[t], 8);
        qcol[t] += __shfl_xor_sync(0xffffffff, qcol[t], 16);
    }
    if (g == 0) {
#pragma unroll
        for (int nt = 0; nt < 8; nt++) {
            int c = wcol + nt * 8 + 2 * tg;
            atomicAdd(&g_sum[c],     scol[nt * 2]);
            atomicAdd(&g_sum[c + 1], scol[nt * 2 + 1]);
            atomicAdd(&g_sumsq[c],     qcol[nt * 2]);
            atomicAdd(&g_sumsq[c + 1], qcol[nt * 2 + 1]);
        }
    }
}

// ---- hidden GEMM: K=128 (16 ks), 128 cols (16 groups) ----
#define GT_WFRAG_F4 (16 * 16 * 32)
#define GT_LDX 132
#define GT_XHI (GT_WFRAG_F4 * 4)
#define GT_XLO (GT_WFRAG_F4 * 4 + 64 * GT_LDX)
#define GT_SMEM ((GT_WFRAG_F4 * 4 + 2 * 64 * GT_LDX) * 4)
#define GT_GRID 148
__global__ void __launch_bounds__(256, 1) k_gemm_tf32(const float* __restrict__ W,
                                                      const float* __restrict__ b,
                                                      int slot) {
    extern __shared__ float sm[];
    float4* Wfrag = (float4*)sm;
    float* xhi = sm + GT_XHI;
    float* xlo = sm + GT_XLO;
    int tid = threadIdx.x, lane = tid & 31, warp = tid >> 5;
    int g = lane >> 2, tg = lane & 3;

    for (int i = tid; i < GT_WFRAG_F4; i += 256) {
        int li = i & 31, cg = (i >> 5) & 15, ks = i >> 9;
        int c = cg * 8 + (li >> 2);
        int k = ks * 8 + (li & 3);
        float v0 = W[k * HID + c];
        float v1 = W[(k + 4) * HID + c];
        unsigned int h0, l0, h1, l1;
        tf32_split(v0, h0, l0);
        tf32_split(v1, h1, l1);
        float4 f;
        f.x = __uint_as_float(h0); f.y = __uint_as_float(h1);
        f.z = __uint_as_float(l0); f.w = __uint_as_float(l1);
        Wfrag[i] = f;
    }

    int wrow = (warp & 3) * 16;
    int wcol = (warp >> 2) * 64;
    int ntbase = (warp >> 2) * 8;
    float bcx[8], bcy[8];
#pragma unroll
    for (int nt = 0; nt < 8; nt++) {
        int c = wcol + nt * 8 + 2 * tg;
        bcx[nt] = __ldg(&b[c]);
        bcy[nt] = __ldg(&b[c + 1]);
    }
    float scol[16], qcol[16];
#pragma unroll
    for (int t = 0; t < 16; t++) { scol[t] = 0.f; qcol[t] = 0.f; }

    for (int rb = blockIdx.x * 64; rb < NN; rb += GT_GRID * 64) {
        __syncthreads();
        for (int i = tid; i < 64 * 32; i += 256) {
            int row = i >> 5, t4 = i & 31;
            int gr = rb + row;
            float4 v = (gr < NN) ? ((const float4*)g_agg)[(size_t)gr * 32 + t4]
                                 : make_float4(0.f, 0.f, 0.f, 0.f);
            uint4 hi, lo;
            tf32_split(v.x, hi.x, lo.x);
            tf32_split(v.y, hi.y, lo.y);
            tf32_split(v.z, hi.z, lo.z);
            tf32_split(v.w, hi.w, lo.w);
            *(uint4*)(xhi + row * GT_LDX + t4 * 4) = hi;
            *(uint4*)(xlo + row * GT_LDX + t4 * 4) = lo;
        }
        __syncthreads();

        float d[8][4];
#pragma unroll
        for (int nt = 0; nt < 8; nt++) { d[nt][0]=0.f; d[nt][1]=0.f; d[nt][2]=0.f; d[nt][3]=0.f; }

#pragma unroll
        for (int ks = 0; ks < 16; ks++) {
            int k0 = ks * 8;
            unsigned int ah0 = __float_as_uint(xhi[(wrow + g) * GT_LDX + k0 + tg]);
            unsigned int ah1 = __float_as_uint(xhi[(wrow + g + 8) * GT_LDX + k0 + tg]);
            unsigned int ah2 = __float_as_uint(xhi[(wrow + g) * GT_LDX + k0 + tg + 4]);
            unsigned int ah3 = __float_as_uint(xhi[(wrow + g + 8) * GT_LDX + k0 + tg + 4]);
            unsigned int al0 = __float_as_uint(xlo[(wrow + g) * GT_LDX + k0 + tg]);
            unsigned int al1 = __float_as_uint(xlo[(wrow + g + 8) * GT_LDX + k0 + tg]);
            unsigned int al2 = __float_as_uint(xlo[(wrow + g) * GT_LDX + k0 + tg + 4]);
            unsigned int al3 = __float_as_uint(xlo[(wrow + g + 8) * GT_LDX + k0 + tg + 4]);
            const float4* wf = Wfrag + (ks * 16 + ntbase) * 32 + lane;
#pragma unroll
            for (int nt = 0; nt < 8; nt++) {
                float4 bf = wf[nt * 32];
                unsigned int bh0 = __float_as_uint(bf.x);
                unsigned int bh1 = __float_as_uint(bf.y);
                unsigned int bl0 = __float_as_uint(bf.z);
                unsigned int bl1 = __float_as_uint(bf.w);
#define MMA(A0,A1,A2,A3,B0,B1) \
                asm volatile( \
                    "mma.sync.aligned.m16n8k8.row.col.f32.tf32.tf32.f32 " \
                    "{%0,%1,%2,%3}, {%4,%5,%6,%7}, {%8,%9}, {%0,%1,%2,%3};" \
                    : "+f"(d[nt][0]), "+f"(d[nt][1]), "+f"(d[nt][2]), "+f"(d[nt][3]) \
                    : "r"(A0), "r"(A1), "r"(A2), "r"(A3), "r"(B0), "r"(B1));
                MMA(ah0, ah1, ah2, ah3, bh0, bh1)
                MMA(ah0, ah1, ah2, ah3, bl0, bl1)
                MMA(al0, al1, al2, al3, bh0, bh1)
#undef MMA
            }
        }

        int r0 = rb + wrow + g;
        int r1 = r0 + 8;
        bool v0 = r0 < NN, v1 = r1 < NN;
        float nd0 = v0 ? g_norm_dst[r0] : 0.f;
        float nd1 = v1 ? g_norm_dst[r1] : 0.f;
#pragma unroll
        for (int nt = 0; nt < 8; nt++) {
            int c = wcol + nt * 8 + 2 * tg;
            if (v0) {
                float yx = d[nt][0] * nd0 + bcx[nt];
                float yy = d[nt][1] * nd0 + bcy[nt];
                *(float2*)(g_x + (size_t)r0 * HID + c) = make_float2(yx, yy);
                scol[nt * 2] += yx;     qcol[nt * 2]     = fmaf(yx, yx, qcol[nt * 2]);
                scol[nt * 2 + 1] += yy; qcol[nt * 2 + 1] = fmaf(yy, yy, qcol[nt * 2 + 1]);
            }
            if (v1) {
                float yx = d[nt][2] * nd1 + bcx[nt];
                float yy = d[nt][3] * nd1 + bcy[nt];
                *(float2*)(g_x + (size_t)r1 * HID + c) = make_float2(yx, yy);
                scol[nt * 2] += yx;     qcol[nt * 2]     = fmaf(yx, yx, qcol[nt * 2]);
                scol[nt * 2 + 1] += yy; qcol[nt * 2 + 1] = fmaf(yy, yy, qcol[nt * 2 + 1]);
            }
        }
    }

#pragma unroll
    for (int t = 0; t < 16; t++) {
        scol[t] += __shfl_xor_sync(0xffffffff, scol[t], 4);
        scol[t] += __shfl_xor_sync(0xffffffff, scol[t], 8);
        scol[t] += __shfl_xor_sync(0xffffffff, scol[t], 16);
        qcol[t] += __shfl_xor_sync(0xffffffff, qcol[t], 4);
        qcol[t] += __shfl_xor_sync(0xffffffff, qcol[t], 8);
        qcol[t] += __shfl_xor_sync(0xffffffff, qcol[t], 16);
    }
    if (g == 0) {
        float* gsum = g_sum + slot * HID;
        float* gsq  = g_sumsq + slot * HID;
#pragma unroll
        for (int nt = 0; nt < 8; nt++) {
            int c = wcol + nt * 8 + 2 * tg;
            atomicAdd(&gsum[c],     scol[nt * 2]);
            atomicAdd(&gsum[c + 1], scol[nt * 2 + 1]);
            atomicAdd(&gsq[c],      qcol[nt * 2]);
            atomicAdd(&gsq[c + 1],  qcol[nt * 2 + 1]);
        }
    }
}

// ---- final FC: K=128 (16 ks), 64 cols (8 groups); BN2+ReLU fused in staging ----
#define FC_WFRAG_F4 (16 * 8 * 32)
#define FC_LDX 132
#define FC_XHI (FC_WFRAG_F4 * 4)
#define FC_XLO (FC_WFRAG_F4 * 4 + 64 * FC_LDX)
#define FC_SC  (FC_WFRAG_F4 * 4 + 2 * 64 * FC_LDX)
#define FC_SMEM ((FC_WFRAG_F4 * 4 + 2 * 64 * FC_LDX + 2 * HID) * 4)
#define FC_GRID 148
__global__ void __launch_bounds__(256, 1) k_fc_tf32(const float* __restrict__ W,
                                                    const float* __restrict__ b,
                                                    const float* __restrict__ gam,
                                                    const float* __restrict__ bet,
                                                    float* __restrict__ out) {
    extern __shared__ float sm[];
    float4* Wfrag = (float4*)sm;
    float* xhi = sm + FC_XHI;
    float* xlo = sm + FC_XLO;
    float* scs = sm + FC_SC;
    float* shs = scs + HID;
    int tid = threadIdx.x, lane = tid & 31, warp = tid >> 5;
    int g = lane >> 2, tg = lane & 3;

    if (tid < HID) {
        float inv_n = 1.f / (float)NN;
        float mu = g_sum[2 * HID + tid] * inv_n;
        float var = g_sumsq[2 * HID + tid] * inv_n - mu * mu;
        float sc = gam[tid] * rsqrtf(var + BN_EPS);
        scs[tid] = sc;
        shs[tid] = bet[tid] - mu * sc;
    }
    for (int i = tid; i < FC_WFRAG_F4; i += 256) {
        int li = i & 31, cg = (i >> 5) & 7, ks = i >> 8;
        int c = cg * 8 + (li >> 2);
        int k = ks * 8 + (li & 3);
        float v0 = W[k * OUTC + c];
        float v1 = W[(k + 4) * OUTC + c];
        unsigned int h0, l0, h1, l1;
        tf32_split(v0, h0, l0);
        tf32_split(v1, h1, l1);
        float4 f;
        f.x = __uint_as_float(h0); f.y = __uint_as_float(h1);
        f.z = __uint_as_float(l0); f.w = __uint_as_float(l1);
        Wfrag[i] = f;
    }

    int wrow = (warp & 3) * 16;
    int wcol = (warp >> 2) * 32;
    int ntbase = (warp >> 2) * 4;
    float bcx[4], bcy[4];
#pragma unroll
    for (int nt = 0; nt < 4; nt++) {
        int c = wcol + nt * 8 + 2 * tg;
        bcx[nt] = __ldg(&b[c]);
        bcy[nt] = __ldg(&b[c + 1]);
    }
    __syncthreads();

    for (int rb = blockIdx.x * 64; rb < NN; rb += FC_GRID * 64) {
        __syncthreads();
        for (int i = tid; i < 64 * 32; i += 256) {
            int row = i >> 5, t4 = i & 31;
            int gr = rb + row;
            float4 v = (gr < NN) ? ((const float4*)g_x)[(size_t)gr * 32 + t4]
                                 : make_float4(0.f, 0.f, 0.f, 0.f);
            int k = t4 * 4;
            v.x = fmaxf(fmaf(v.x, scs[k + 0], shs[k + 0]), 0.f);
            v.y = fmaxf(fmaf(v.y, scs[k + 1], shs[k + 1]), 0.f);
            v.z = fmaxf(fmaf(v.z, scs[k + 2], shs[k + 2]), 0.f);
            v.w = fmaxf(fmaf(v.w, scs[k + 3], shs[k + 3]), 0.f);
            uint4 hi, lo;
            tf32_split(v.x, hi.x, lo.x);
            tf32_split(v.y, hi.y, lo.y);
            tf32_split(v.z, hi.z, lo.z);
            tf32_split(v.w, hi.w, lo.w);
            *(uint4*)(xhi + row * FC_LDX + t4 * 4) = hi;
            *(uint4*)(xlo + row * FC_LDX + t4 * 4) = lo;
        }
        __syncthreads();

        float d[4][4];
#pragma unroll
        for (int nt = 0; nt < 4; nt++) { d[nt][0]=0.f; d[nt][1]=0.f; d[nt][2]=0.f; d[nt][3]=0.f; }

#pragma unroll
        for (int ks = 0; ks < 16; ks++) {
            int k0 = ks * 8;
            unsigned int ah0 = __float_as_uint(xhi[(wrow + g) * FC_LDX + k0 + tg]);
            unsigned int ah1 = __float_as_uint(xhi[(wrow + g + 8) * FC_LDX + k0 + tg]);
            unsigned int ah2 = __float_as_uint(xhi[(wrow + g) * FC_LDX + k0 + tg + 4]);
            unsigned int ah3 = __float_as_uint(xhi[(wrow + g + 8) * FC_LDX + k0 + tg + 4]);
            unsigned int al0 = __float_as_uint(xlo[(wrow + g) * FC_LDX + k0 + tg]);
            unsigned int al1 = __float_as_uint(xlo[(wrow + g + 8) * FC_LDX + k0 + tg]);
            unsigned int al2 = __float_as_uint(xlo[(wrow + g) * FC_LDX + k0 + tg + 4]);
            unsigned int al3 = __float_as_uint(xlo[(wrow + g + 8) * FC_LDX + k0 + tg + 4]);
            const float4* wf = Wfrag + (ks * 8 + ntbase) * 32 + lane;
#pragma unroll
            for (int nt = 0; nt < 4; nt++) {
                float4 bf = wf[nt * 32];
                unsigned int bh0 = __float_as_uint(bf.x);
                unsigned int bh1 = __float_as_uint(bf.y);
                unsigned int bl0 = __float_as_uint(bf.z);
                unsigned int bl1 = __float_as_uint(bf.w);
#define MMA(A0,A1,A2,A3,B0,B1) \
                asm volatile( \
                    "mma.sync.aligned.m16n8k8.row.col.f32.tf32.tf32.f32 " \
                    "{%0,%1,%2,%3}, {%4,%5,%6,%7}, {%8,%9}, {%0,%1,%2,%3};" \
                    : "+f"(d[nt][0]), "+f"(d[nt][1]), "+f"(d[nt][2]), "+f"(d[nt][3]) \
                    : "r"(A0), "r"(A1), "r"(A2), "r"(A3), "r"(B0), "r"(B1));
                MMA(ah0, ah1, ah2, ah3, bh0, bh1)
                MMA(ah0, ah1, ah2, ah3, bl0, bl1)
                MMA(al0, al1, al2, al3, bh0, bh1)
#undef MMA
            }
        }

        int r0 = rb + wrow + g;
        int r1 = r0 + 8;
#pragma unroll
        for (int nt = 0; nt < 4; nt++) {
            int c = wcol + nt * 8 + 2 * tg;
            if (r0 < NN)
                *(float2*)(out + (size_t)r0 * OUTC + c) =
                    make_float2(d[nt][0] + bcx[nt], d[nt][1] + bcy[nt]);
            if (r1 < NN)
                *(float2*)(out + (size_t)r1 * OUTC + c) =
                    make_float2(d[nt][2] + bcx[nt], d[nt][3] + bcy[nt]);
        }
    }
}

// ---------------- launch ----------------
extern "C" void kernel_launch(void* const* d_in, const int* in_sizes, int n_in,
                              void* d_out, int out_size) {
    const float* h   = (const float*)d_in[0];
    const int*   src = (const int*)d_in[1];
    const int*   dst = (const int*)d_in[2];
    const float* w0  = (const float*)d_in[3];
    const float* b0  = (const float*)d_in[4];
    const float* w1  = (const float*)d_in[5];
    const float* b1  = (const float*)d_in[6];
    const float* w2  = (const float*)d_in[7];
    const float* b2  = (const float*)d_in[8];
    const float* g0  = (const float*)d_in[9];
    const float* bt0 = (const float*)d_in[10];
    const float* g1  = (const float*)d_in[11];
    const float* bt1 = (const float*)d_in[12];
    const float* g2  = (const float*)d_in[13];
    const float* bt2 = (const float*)d_in[14];
    const float* wfc = (const float*)d_in[15];
    const float* bfc = (const float*)d_in[16];
    float* out = (float*)d_out;

    cudaFuncSetAttribute(k_gemm_tf32, cudaFuncAttributeMaxDynamicSharedMemorySize, GT_SMEM);
    cudaFuncSetAttribute(k_gemm_l0_tf32, cudaFuncAttributeMaxDynamicSharedMemorySize, L0_SMEM);
    cudaFuncSetAttribute(k_fc_tf32, cudaFuncAttributeMaxDynamicSharedMemorySize, FC_SMEM);

    // graph prep
    k_zero_deg<<<(NN + 255) / 256, 256>>>();
    k_degrees<<<(NE / 4 + 255) / 256, 256>>>(src, dst);
    k_nodeprep_alloc<<<(NN + 255) / 256, 256>>>(h, out);
    k_fill<<<(NE / 4 + 255) / 256, 256>>>(src, dst);

    // ---- layer 0 (26 -> 128), stats -> slot 0 ----
    k_gather26<<<(NN * 32 + 255) / 256, 256>>>();
    k_gemm_l0_tf32<<<L0_GRID, 256, L0_SMEM>>>(w0, b0);

    // ---- layers 1, 2 (128 -> 128), stats -> slots 1, 2 ----
    const float* Ws[2]  = {w1, w2};
    const float* bs[2]  = {b1, b2};
    const float* gs[2]  = {g0, g1};
    const float* bts[2] = {bt0, bt1};
    for (int l = 0; l < 2; l++) {
        k_prescale<<<(NN * (HID / 4) + 255) / 256, 256>>>(gs[l], bts[l], l);
        k_gather128<<<(NN * 32 + 255) / 256, 256>>>();
        k_gemm_tf32<<<GT_GRID, 256, GT_SMEM>>>(Ws[l], bs[l], l + 1);
    }

    // ---- final FC (128 -> 64), BN2+ReLU from slot 2 fused in staging ----
    k_fc_tf32<<<FC_GRID, 256, FC_SMEM>>>(wfc, bfc, g2, bt2, out);
}

// round 16
// speedup vs baseline: 1.1075x; 1.1075x over previous
#include <cuda_runtime.h>
#include <cuda_fp16.h>

#define NN   100000
#define NE   1600000
#define INC  26
#define HID  128
#define OUTC 64
#define BN_EPS 1e-5f
#define OUT_ELEMS (NN * OUTC)
#define CSR_CAP (NE + 4 * NN)

// ---------------- device scratch ----------------
__device__ __half g_x16[NN * HID];  // raw layer-0/1 outputs, fp16 (prescale input)
__device__ __half g_xh[NN * HID];   // pre-scaled activations, fp16 (gather input)
__device__ __half g_h16[NN * 32];   // layer-0 messages: half(h * norm_src), padded to 32ch
__device__ float  g_agg[NN * HID];  // gather accumulator; layer-2 output written fp32 in place
__device__ float  g_norm_src[NN];
__device__ float  g_norm_dst[NN];
__device__ int    g_deg_out_i[NN];
__device__ int    g_deg_in_i[NN];
__device__ int    g_rowptr[NN];
__device__ int    g_cursor[NN];
__device__ int    g_csr_src[CSR_CAP];
__device__ int    g_total;
__device__ float  g_sum[3 * HID];
__device__ float  g_sumsq[3 * HID];

__constant__ float c_wtable[26] = {
    0.7f,0.9f,0.7f,0.9f,0.3f,0.7f,0.3f,0.9f,0.3f,0.3f,0.9f,0.7f,0.1f,
    0.9f,0.5f,0.9f,0.5f,0.5f,0.1f,0.3f,0.7f,0.9f,0.9f,0.9f,0.9f,0.9f};

__device__ __forceinline__ void tf32_split(float v, unsigned int& hi, unsigned int& lo) {
    asm("cvt.rna.tf32.f32 %0, %1;" : "=r"(hi) : "f"(v));
    float rem = v - __uint_as_float(hi);
    asm("cvt.rna.tf32.f32 %0, %1;" : "=r"(lo) : "f"(rem));
}

// ---------------- prep kernels ----------------
__global__ void k_zero_deg() {
    int n = blockIdx.x * blockDim.x + threadIdx.x;
    if (n < NN) { g_deg_out_i[n] = 0; g_deg_in_i[n] = 0; }
    if (n < 3 * HID) { g_sum[n] = 0.f; g_sumsq[n] = 0.f; }
    if (n == 0) g_total = 0;
}

__global__ void k_degrees(const int* __restrict__ src, const int* __restrict__ dst) {
    int t = blockIdx.x * blockDim.x + threadIdx.x;
    if (t >= NE / 4) return;
    int4 s = ((const int4*)src)[t];
    int4 d = ((const int4*)dst)[t];
    atomicAdd(&g_deg_out_i[s.x], 1);
    atomicAdd(&g_deg_out_i[s.y], 1);
    atomicAdd(&g_deg_out_i[s.z], 1);
    atomicAdd(&g_deg_out_i[s.w], 1);
    atomicAdd(&g_deg_in_i[d.x], 1);
    atomicAdd(&g_deg_in_i[d.y], 1);
    atomicAdd(&g_deg_in_i[d.z], 1);
    atomicAdd(&g_deg_in_i[d.w], 1);
}

__global__ void k_nodeprep_alloc(const float* __restrict__ h, float* __restrict__ out) {
    int n = blockIdx.x * blockDim.x + threadIdx.x;
    int lane = threadIdx.x & 31;

    int dpad = 0, deg_in = 0;
    if (n < NN) {
        deg_in = g_deg_in_i[n];
        dpad = (deg_in + 3) & ~3;
    }
    int incl = dpad;
#pragma unroll
    for (int o = 1; o < 32; o <<= 1) {
        int t = __shfl_up_sync(0xffffffff, incl, o);
        if (lane >= o) incl += t;
    }
    int wtotal = __shfl_sync(0xffffffff, incl, 31);
    int base = 0;
    if (lane == 0) base = atomicAdd(&g_total, wtotal);
    base = __shfl_sync(0xffffffff, base, 0);
    if (n >= NN) return;
    int pos = base + incl - dpad;
    g_rowptr[n] = pos;
    g_cursor[n] = pos;

    const float* hr = h + (size_t)n * INC;
    float hv[INC];
    float best = -1e30f;
    int bi = 0;
#pragma unroll
    for (int c = 0; c < INC; c++) {
        float v = hr[c];
        hv[c] = v;
        if (v > best) { best = v; bi = c; }
    }
    out[OUT_ELEMS + n] = c_wtable[bi];
    float ns = rsqrtf(fmaxf((float)g_deg_out_i[n], 1.f));
    g_norm_src[n] = ns;
    g_norm_dst[n] = rsqrtf(fmaxf((float)deg_in, 1.f));
    unsigned int* dsth = (unsigned int*)g_h16 + (size_t)n * 16;
#pragma unroll
    for (int j = 0; j < 13; j++) {
        __half2 p = __floats2half2_rn(hv[2 * j] * ns, hv[2 * j + 1] * ns);
        dsth[j] = *(unsigned int*)&p;
    }
    dsth[13] = 0; dsth[14] = 0; dsth[15] = 0;
}

__global__ void k_fill(const int* __restrict__ src, const int* __restrict__ dst) {
    int t = blockIdx.x * blockDim.x + threadIdx.x;
    if (t >= NE / 4) return;
    int4 s = ((const int4*)src)[t];
    int4 d = ((const int4*)dst)[t];
    g_csr_src[atomicAdd(&g_cursor[d.x], 1)] = s.x;
    g_csr_src[atomicAdd(&g_cursor[d.y], 1)] = s.y;
    g_csr_src[atomicAdd(&g_cursor[d.z], 1)] = s.z;
    g_csr_src[atomicAdd(&g_cursor[d.w], 1)] = s.w;
}

// ---------------- layer-0 gather: fp16 packed rows, half-warp per edge ----------------
__global__ void k_gather26() {
    int gid = blockIdx.x * blockDim.x + threadIdx.x;
    int n = gid >> 5;
    int lane = gid & 31;
    if (n >= NN) return;
    int sub = lane & 15;
    int w = lane >> 4;
    int start = g_rowptr[n];
    int cnt = g_deg_in_i[n];
    const int* cs = g_csr_src + start;
    const unsigned int* xh = (const unsigned int*)g_h16;
    float2 acc = make_float2(0.f, 0.f);
    int i = 0;
    for (; i + 4 <= cnt; i += 4) {
        int sA = cs[i + w];
        int sB = cs[i + 2 + w];
        unsigned int pA = __ldg(xh + (size_t)sA * 16 + sub);
        unsigned int pB = __ldg(xh + (size_t)sB * 16 + sub);
        float2 a = __half22float2(*(__half2*)&pA);
        float2 b = __half22float2(*(__half2*)&pB);
        acc.x += a.x + b.x;
        acc.y += a.y + b.y;
    }
    for (; i < cnt; i += 2) {
        int e = i + w;
        if (e < cnt) {
            int s = cs[e];
            unsigned int p = __ldg(xh + (size_t)s * 16 + sub);
            float2 a = __half22float2(*(__half2*)&p);
            acc.x += a.x;
            acc.y += a.y;
        }
    }
    acc.x += __shfl_xor_sync(0xffffffff, acc.x, 16);
    acc.y += __shfl_xor_sync(0xffffffff, acc.y, 16);
    if (w == 0) {
        ((float2*)(g_agg + (size_t)n * 32))[sub] = acc;
    }
}

// pre-scale: BN scale/shift from stats slot, then g_xh <- half(relu(bn(g_x16)) * norm_src)
__global__ void k_prescale(const float* __restrict__ g, const float* __restrict__ bt,
                           int slot) {
    __shared__ float scs[HID], shs[HID];
    int tid = threadIdx.x;
    if (tid < HID) {
        float inv_n = 1.f / (float)NN;
        float mu = g_sum[slot * HID + tid] * inv_n;
        float var = g_sumsq[slot * HID + tid] * inv_n - mu * mu;
        float sc = g[tid] * rsqrtf(var + BN_EPS);
        scs[tid] = sc;
        shs[tid] = bt[tid] - mu * sc;
    }
    __syncthreads();
    int i = blockIdx.x * blockDim.x + threadIdx.x;
    if (i >= NN * (HID / 4)) return;
    int lane = i & 31;
    int row = i >> 5;
    float4 sc = *(const float4*)(scs + lane * 4);
    float4 sh = *(const float4*)(shs + lane * 4);
    float ns = g_norm_src[row];
    uint2 p = ((const uint2*)g_x16)[i];
    float2 v01 = __half22float2(*(__half2*)&p.x);
    float2 v23 = __half22float2(*(__half2*)&p.y);
    float2 lo = make_float2(fmaxf(fmaf(v01.x, sc.x, sh.x), 0.f) * ns,
                            fmaxf(fmaf(v01.y, sc.y, sh.y), 0.f) * ns);
    float2 hi = make_float2(fmaxf(fmaf(v23.x, sc.z, sh.z), 0.f) * ns,
                            fmaxf(fmaf(v23.y, sc.w, sh.w), 0.f) * ns);
    __half2 h0 = __float22half2_rn(lo);
    __half2 h1 = __float22half2_rn(hi);
    uint2 packed;
    packed.x = *(unsigned int*)&h0;
    packed.y = *(unsigned int*)&h1;
    ((uint2*)g_xh)[i] = packed;
}

// pure-sum gather, fp16 rows, fp32 accumulation, warp-per-node, MLP=16
__global__ void k_gather128() {
    int gid = blockIdx.x * blockDim.x + threadIdx.x;
    int n = gid >> 5;
    int lane = gid & 31;
    if (n >= NN) return;
    const int* cs = g_csr_src + g_rowptr[n];
    int cnt = g_deg_in_i[n];
    float4 acc = make_float4(0.f, 0.f, 0.f, 0.f);
    const uint2* xh = (const uint2*)g_xh;
    float2 a, bb;
#define ACC(P) \
        a = __half22float2(*(__half2*)&P.x); bb = __half22float2(*(__half2*)&P.y); \
        acc.x += a.x; acc.y += a.y; acc.z += bb.x; acc.w += bb.y;
    int i = 0;
    for (; i + 16 <= cnt; i += 16) {
        int4 ia = *(const int4*)(cs + i);
        int4 ib = *(const int4*)(cs + i + 4);
        int4 ic = *(const int4*)(cs + i + 8);
        int4 id = *(const int4*)(cs + i + 12);
        uint2 p0 = __ldg(xh + (size_t)ia.x * 32 + lane);
        uint2 p1 = __ldg(xh + (size_t)ia.y * 32 + lane);
        uint2 p2 = __ldg(xh + (size_t)ia.z * 32 + lane);
        uint2 p3 = __ldg(xh + (size_t)ia.w * 32 + lane);
        uint2 p4 = __ldg(xh + (size_t)ib.x * 32 + lane);
        uint2 p5 = __ldg(xh + (size_t)ib.y * 32 + lane);
        uint2 p6 = __ldg(xh + (size_t)ib.z * 32 + lane);
        uint2 p7 = __ldg(xh + (size_t)ib.w * 32 + lane);
        uint2 p8 = __ldg(xh + (size_t)ic.x * 32 + lane);
        uint2 p9 = __ldg(xh + (size_t)ic.y * 32 + lane);
        uint2 pa = __ldg(xh + (size_t)ic.z * 32 + lane);
        uint2 pb = __ldg(xh + (size_t)ic.w * 32 + lane);
        uint2 pc = __ldg(xh + (size_t)id.x * 32 + lane);
        uint2 pd = __ldg(xh + (size_t)id.y * 32 + lane);
        uint2 pe = __ldg(xh + (size_t)id.z * 32 + lane);
        uint2 pf = __ldg(xh + (size_t)id.w * 32 + lane);
        ACC(p0) ACC(p1) ACC(p2) ACC(p3) ACC(p4) ACC(p5) ACC(p6) ACC(p7)
        ACC(p8) ACC(p9) ACC(pa) ACC(pb) ACC(pc) ACC(pd) ACC(pe) ACC(pf)
    }
    for (; i + 4 <= cnt; i += 4) {
        int4 ia = *(const int4*)(cs + i);
        uint2 p0 = __ldg(xh + (size_t)ia.x * 32 + lane);
        uint2 p1 = __ldg(xh + (size_t)ia.y * 32 + lane);
        uint2 p2 = __ldg(xh + (size_t)ia.z * 32 + lane);
        uint2 p3 = __ldg(xh + (size_t)ia.w * 32 + lane);
        ACC(p0) ACC(p1) ACC(p2) ACC(p3)
    }
    for (; i < cnt; i++) {
        int s0 = cs[i];
        uint2 p0 = __ldg(xh + (size_t)s0 * 32 + lane);
        ACC(p0)
    }
#undef ACC
    ((float4*)(g_agg + (size_t)n * HID))[lane] = acc;
}

// ============ GEMMs: 3xTF32 with fragment-layout W ============

// ---- layer-0 GEMM: K=32 (4 ks), 128 cols (16 groups), out fp16 ----
#define L0_WFRAG_F4 (4 * 16 * 32)
#define L0_LDX 132
#define L0_XHI (L0_WFRAG_F4 * 4)
#define L0_XLO (L0_WFRAG_F4 * 4 + 64 * L0_LDX)
#define L0_SMEM ((L0_WFRAG_F4 * 4 + 2 * 64 * L0_LDX) * 4)
#define L0_GRID 148
__global__ void __launch_bounds__(256, 1) k_gemm_l0_tf32(const float* __restrict__ W,
                                                         const float* __restrict__ b) {
    extern __shared__ float sm[];
    float4* Wfrag = (float4*)sm;
    float* xhi = sm + L0_XHI;
    float* xlo = sm + L0_XLO;
    int tid = threadIdx.x, lane = tid & 31, warp = tid >> 5;
    int g = lane >> 2, tg = lane & 3;

    for (int i = tid; i < L0_WFRAG_F4; i += 256) {
        int li = i & 31, cg = (i >> 5) & 15, ks = i >> 9;
        int c = cg * 8 + (li >> 2);
        int k = ks * 8 + (li & 3);
        float v0 = (k < INC) ? W[k * HID + c] : 0.f;
        float v1 = (k + 4 < INC) ? W[(k + 4) * HID + c] : 0.f;
        unsigned int h0, l0, h1, l1;
        tf32_split(v0, h0, l0);
        tf32_split(v1, h1, l1);
        float4 f;
        f.x = __uint_as_float(h0); f.y = __uint_as_float(h1);
        f.z = __uint_as_float(l0); f.w = __uint_as_float(l1);
        Wfrag[i] = f;
    }

    int wrow = (warp & 3) * 16;
    int wcol = (warp >> 2) * 64;
    int ntbase = (warp >> 2) * 8;
    float bcx[8], bcy[8];
#pragma unroll
    for (int nt = 0; nt < 8; nt++) {
        int c = wcol + nt * 8 + 2 * tg;
        bcx[nt] = __ldg(&b[c]);
        bcy[nt] = __ldg(&b[c + 1]);
    }
    float scol[16], qcol[16];
#pragma unroll
    for (int t = 0; t < 16; t++) { scol[t] = 0.f; qcol[t] = 0.f; }

    for (int rb = blockIdx.x * 64; rb < NN; rb += L0_GRID * 64) {
        __syncthreads();
        for (int i = tid; i < 64 * 8; i += 256) {
            int row = i >> 3, t4 = i & 7;
            int gr = rb + row;
            float4 v = (gr < NN) ? ((const float4*)g_agg)[(size_t)gr * 8 + t4]
                                 : make_float4(0.f, 0.f, 0.f, 0.f);
            uint4 hi, lo;
            tf32_split(v.x, hi.x, lo.x);
            tf32_split(v.y, hi.y, lo.y);
            tf32_split(v.z, hi.z, lo.z);
            tf32_split(v.w, hi.w, lo.w);
            *(uint4*)(xhi + row * L0_LDX + t4 * 4) = hi;
            *(uint4*)(xlo + row * L0_LDX + t4 * 4) = lo;
        }
        __syncthreads();

        float d[8][4];
#pragma unroll
        for (int nt = 0; nt < 8; nt++) { d[nt][0]=0.f; d[nt][1]=0.f; d[nt][2]=0.f; d[nt][3]=0.f; }

#pragma unroll
        for (int ks = 0; ks < 4; ks++) {
            int k0 = ks * 8;
            unsigned int ah0 = __float_as_uint(xhi[(wrow + g) * L0_LDX + k0 + tg]);
            unsigned int ah1 = __float_as_uint(xhi[(wrow + g + 8) * L0_LDX + k0 + tg]);
            unsigned int ah2 = __float_as_uint(xhi[(wrow + g) * L0_LDX + k0 + tg + 4]);
            unsigned int ah3 = __float_as_uint(xhi[(wrow + g + 8) * L0_LDX + k0 + tg + 4]);
            unsigned int al0 = __float_as_uint(xlo[(wrow + g) * L0_LDX + k0 + tg]);
            unsigned int al1 = __float_as_uint(xlo[(wrow + g + 8) * L0_LDX + k0 + tg]);
            unsigned int al2 = __float_as_uint(xlo[(wrow + g) * L0_LDX + k0 + tg + 4]);
            unsigned int al3 = __float_as_uint(xlo[(wrow + g + 8) * L0_LDX + k0 + tg + 4]);
            const float4* wf = Wfrag + (ks * 16 + ntbase) * 32 + lane;
#pragma unroll
            for (int nt = 0; nt < 8; nt++) {
                float4 bf = wf[nt * 32];
                unsigned int bh0 = __float_as_uint(bf.x);
                unsigned int bh1 = __float_as_uint(bf.y);
                unsigned int bl0 = __float_as_uint(bf.z);
                unsigned int bl1 = __float_as_uint(bf.w);
#define MMA(A0,A1,A2,A3,B0,B1) \
                asm volatile( \
                    "mma.sync.aligned.m16n8k8.row.col.f32.tf32.tf32.f32 " \
                    "{%0,%1,%2,%3}, {%4,%5,%6,%7}, {%8,%9}, {%0,%1,%2,%3};" \
                    : "+f"(d[nt][0]), "+f"(d[nt][1]), "+f"(d[nt][2]), "+f"(d[nt][3]) \
                    : "r"(A0), "r"(A1), "r"(A2), "r"(A3), "r"(B0), "r"(B1));
                MMA(ah0, ah1, ah2, ah3, bh0, bh1)
                MMA(ah0, ah1, ah2, ah3, bl0, bl1)
                MMA(al0, al1, al2, al3, bh0, bh1)
#undef MMA
            }
        }

        int r0 = rb + wrow + g;
        int r1 = r0 + 8;
        bool v0 = r0 < NN, v1 = r1 < NN;
        float nd0 = v0 ? g_norm_dst[r0] : 0.f;
        float nd1 = v1 ? g_norm_dst[r1] : 0.f;
#pragma unroll
        for (int nt = 0; nt < 8; nt++) {
            int c = wcol + nt * 8 + 2 * tg;
            if (v0) {
                float yx = d[nt][0] * nd0 + bcx[nt];
                float yy = d[nt][1] * nd0 + bcy[nt];
                __half2 hp = __floats2half2_rn(yx, yy);
                *(unsigned int*)(g_x16 + (size_t)r0 * HID + c) = *(unsigned int*)&hp;
                scol[nt * 2] += yx;     qcol[nt * 2]     = fmaf(yx, yx, qcol[nt * 2]);
                scol[nt * 2 + 1] += yy; qcol[nt * 2 + 1] = fmaf(yy, yy, qcol[nt * 2 + 1]);
            }
            if (v1) {
                float yx = d[nt][2] * nd1 + bcx[nt];
                float yy = d[nt][3] * nd1 + bcy[nt];
                __half2 hp = __floats2half2_rn(yx, yy);
                *(unsigned int*)(g_x16 + (size_t)r1 * HID + c) = *(unsigned int*)&hp;
                scol[nt * 2] += yx;     qcol[nt * 2]     = fmaf(yx, yx, qcol[nt * 2]);
                scol[nt * 2 + 1] += yy; qcol[nt * 2 + 1] = fmaf(yy, yy, qcol[nt * 2 + 1]);
            }
        }
    }

#pragma unroll
    for (int t = 0; t < 16; t++) {
        scol[t] += __shfl_xor_sync(0xffffffff, scol[t], 4);
        scol[t] += __shfl_xor_sync(0xffffffff, scol[t], 8);
        scol[t] += __shfl_xor_sync(0xffffffff, scol[t], 16);
        qcol[t] += __shfl_xor_sync(0xffffffff, qcol[t], 4);
        qcol[t] += __shfl_xor_sync(0xffffffff, qcol[t], 8);
        qcol[t] += __shfl_xor_sync(0xffffffff, qcol[t], 16);
    }
    if (g == 0) {
#pragma unroll
        for (int nt = 0; nt < 8; nt++) {
            int c = wcol + nt * 8 + 2 * tg;
            atomicAdd(&g_sum[c],     scol[nt * 2]);
            atomicAdd(&g_sum[c + 1], scol[nt * 2 + 1]);
            atomicAdd(&g_sumsq[c],     qcol[nt * 2]);
            atomicAdd(&g_sumsq[c + 1], qcol[nt * 2 + 1]);
        }
    }
}

// ---- hidden GEMM: K=128 (16 ks), 128 cols; writeFp32 selects epilogue target ----
#define GT_WFRAG_F4 (16 * 16 * 32)
#define GT_LDX 132
#define GT_XHI (GT_WFRAG_F4 * 4)
#define GT_XLO (GT_WFRAG_F4 * 4 + 64 * GT_LDX)
#define GT_SMEM ((GT_WFRAG_F4 * 4 + 2 * 64 * GT_LDX) * 4)
#define GT_GRID 148
__global__ void __launch_bounds__(256, 1) k_gemm_tf32(const float* __restrict__ W,
                                                      const float* __restrict__ b,
                                                      int slot, int writeFp32) {
    extern __shared__ float sm[];
    float4* Wfrag = (float4*)sm;
    float* xhi = sm + GT_XHI;
    float* xlo = sm + GT_XLO;
    int tid = threadIdx.x, lane = tid & 31, warp = tid >> 5;
    int g = lane >> 2, tg = lane & 3;

    for (int i = tid; i < GT_WFRAG_F4; i += 256) {
        int li = i & 31, cg = (i >> 5) & 15, ks = i >> 9;
        int c = cg * 8 + (li >> 2);
        int k = ks * 8 + (li & 3);
        float v0 = W[k * HID + c];
        float v1 = W[(k + 4) * HID + c];
        unsigned int h0, l0, h1, l1;
        tf32_split(v0, h0, l0);
        tf32_split(v1, h1, l1);
        float4 f;
        f.x = __uint_as_float(h0); f.y = __uint_as_float(h1);
        f.z = __uint_as_float(l0); f.w = __uint_as_float(l1);
        Wfrag[i] = f;
    }

    int wrow = (warp & 3) * 16;
    int wcol = (warp >> 2) * 64;
    int ntbase = (warp >> 2) * 8;
    float bcx[8], bcy[8];
#pragma unroll
    for (int nt = 0; nt < 8; nt++) {
        int c = wcol + nt * 8 + 2 * tg;
        bcx[nt] = __ldg(&b[c]);
        bcy[nt] = __ldg(&b[c + 1]);
    }
    float scol[16], qcol[16];
#pragma unroll
    for (int t = 0; t < 16; t++) { scol[t] = 0.f; qcol[t] = 0.f; }

    for (int rb = blockIdx.x * 64; rb < NN; rb += GT_GRID * 64) {
        __syncthreads();
        for (int i = tid; i < 64 * 32; i += 256) {
            int row = i >> 5, t4 = i & 31;
            int gr = rb + row;
            float4 v = (gr < NN) ? ((const float4*)g_agg)[(size_t)gr * 32 + t4]
                                 : make_float4(0.f, 0.f, 0.f, 0.f);
            uint4 hi, lo;
            tf32_split(v.x, hi.x, lo.x);
            tf32_split(v.y, hi.y, lo.y);
            tf32_split(v.z, hi.z, lo.z);
            tf32_split(v.w, hi.w, lo.w);
            *(uint4*)(xhi + row * GT_LDX + t4 * 4) = hi;
            *(uint4*)(xlo + row * GT_LDX + t4 * 4) = lo;
        }
        __syncthreads();

        float d[8][4];
#pragma unroll
        for (int nt = 0; nt < 8; nt++) { d[nt][0]=0.f; d[nt][1]=0.f; d[nt][2]=0.f; d[nt][3]=0.f; }

#pragma unroll
        for (int ks = 0; ks < 16; ks++) {
            int k0 = ks * 8;
            unsigned int ah0 = __float_as_uint(xhi[(wrow + g) * GT_LDX + k0 + tg]);
            unsigned int ah1 = __float_as_uint(xhi[(wrow + g + 8) * GT_LDX + k0 + tg]);
            unsigned int ah2 = __float_as_uint(xhi[(wrow + g) * GT_LDX + k0 + tg + 4]);
            unsigned int ah3 = __float_as_uint(xhi[(wrow + g + 8) * GT_LDX + k0 + tg + 4]);
            unsigned int al0 = __float_as_uint(xlo[(wrow + g) * GT_LDX + k0 + tg]);
            unsigned int al1 = __float_as_uint(xlo[(wrow + g + 8) * GT_LDX + k0 + tg]);
            unsigned int al2 = __float_as_uint(xlo[(wrow + g) * GT_LDX + k0 + tg + 4]);
            unsigned int al3 = __float_as_uint(xlo[(wrow + g + 8) * GT_LDX + k0 + tg + 4]);
            const float4* wf = Wfrag + (ks * 16 + ntbase) * 32 + lane;
#pragma unroll
            for (int nt = 0; nt < 8; nt++) {
                float4 bf = wf[nt * 32];
                unsigned int bh0 = __float_as_uint(bf.x);
                unsigned int bh1 = __float_as_uint(bf.y);
                unsigned int bl0 = __float_as_uint(bf.z);
                unsigned int bl1 = __float_as_uint(bf.w);
#define MMA(A0,A1,A2,A3,B0,B1) \
                asm volatile( \
                    "mma.sync.aligned.m16n8k8.row.col.f32.tf32.tf32.f32 " \
                    "{%0,%1,%2,%3}, {%4,%5,%6,%7}, {%8,%9}, {%0,%1,%2,%3};" \
                    : "+f"(d[nt][0]), "+f"(d[nt][1]), "+f"(d[nt][2]), "+f"(d[nt][3]) \
                    : "r"(A0), "r"(A1), "r"(A2), "r"(A3), "r"(B0), "r"(B1));
                MMA(ah0, ah1, ah2, ah3, bh0, bh1)
                MMA(ah0, ah1, ah2, ah3, bl0, bl1)
                MMA(al0, al1, al2, al3, bh0, bh1)
#undef MMA
            }
        }

        int r0 = rb + wrow + g;
        int r1 = r0 + 8;
        bool v0 = r0 < NN, v1 = r1 < NN;
        float nd0 = v0 ? g_norm_dst[r0] : 0.f;
        float nd1 = v1 ? g_norm_dst[r1] : 0.f;
#pragma unroll
        for (int nt = 0; nt < 8; nt++) {
            int c = wcol + nt * 8 + 2 * tg;
            if (v0) {
                float yx = d[nt][0] * nd0 + bcx[nt];
                float yy = d[nt][1] * nd0 + bcy[nt];
                if (writeFp32) {
                    *(float2*)(g_agg + (size_t)r0 * HID + c) = make_float2(yx, yy);
                } else {
                    __half2 hp = __floats2half2_rn(yx, yy);
                    *(unsigned int*)(g_x16 + (size_t)r0 * HID + c) = *(unsigned int*)&hp;
                }
                scol[nt * 2] += yx;     qcol[nt * 2]     = fmaf(yx, yx, qcol[nt * 2]);
                scol[nt * 2 + 1] += yy; qcol[nt * 2 + 1] = fmaf(yy, yy, qcol[nt * 2 + 1]);
            }
            if (v1) {
                float yx = d[nt][2] * nd1 + bcx[nt];
                float yy = d[nt][3] * nd1 + bcy[nt];
                if (writeFp32) {
                    *(float2*)(g_agg + (size_t)r1 * HID + c) = make_float2(yx, yy);
                } else {
                    __half2 hp = __floats2half2_rn(yx, yy);
                    *(unsigned int*)(g_x16 + (size_t)r1 * HID + c) = *(unsigned int*)&hp;
                }
                scol[nt * 2] += yx;     qcol[nt * 2]     = fmaf(yx, yx, qcol[nt * 2]);
                scol[nt * 2 + 1] += yy; qcol[nt * 2 + 1] = fmaf(yy, yy, qcol[nt * 2 + 1]);
            }
        }
    }

#pragma unroll
    for (int t = 0; t < 16; t++) {
        scol[t] += __shfl_xor_sync(0xffffffff, scol[t], 4);
        scol[t] += __shfl_xor_sync(0xffffffff, scol[t], 8);
        scol[t] += __shfl_xor_sync(0xffffffff, scol[t], 16);
        qcol[t] += __shfl_xor_sync(0xffffffff, qcol[t], 4);
        qcol[t] += __shfl_xor_sync(0xffffffff, qcol[t], 8);
        qcol[t] += __shfl_xor_sync(0xffffffff, qcol[t], 16);
    }
    if (g == 0) {
        float* gsum = g_sum + slot * HID;
        float* gsq  = g_sumsq + slot * HID;
#pragma unroll
        for (int nt = 0; nt < 8; nt++) {
            int c = wcol + nt * 8 + 2 * tg;
            atomicAdd(&gsum[c],     scol[nt * 2]);
            atomicAdd(&gsum[c + 1], scol[nt * 2 + 1]);
            atomicAdd(&gsq[c],      qcol[nt * 2]);
            atomicAdd(&gsq[c + 1],  qcol[nt * 2 + 1]);
        }
    }
}

// ---- final FC: reads fp32 g_agg; BN2+ReLU fused in staging ----
#define FC_WFRAG_F4 (16 * 8 * 32)
#define FC_LDX 132
#define FC_XHI (FC_WFRAG_F4 * 4)
#define FC_XLO (FC_WFRAG_F4 * 4 + 64 * FC_LDX)
#define FC_SC  (FC_WFRAG_F4 * 4 + 2 * 64 * FC_LDX)
#define FC_SMEM ((FC_WFRAG_F4 * 4 + 2 * 64 * FC_LDX + 2 * HID) * 4)
#define FC_GRID 148
__global__ void __launch_bounds__(256, 1) k_fc_tf32(const float* __restrict__ W,
                                                    const float* __restrict__ b,
                                                    const float* __restrict__ gam,
                                                    const float* __restrict__ bet,
                                                    float* __restrict__ out) {
    extern __shared__ float sm[];
    float4* Wfrag = (float4*)sm;
    float* xhi = sm + FC_XHI;
    float* xlo = sm + FC_XLO;
    float* scs = sm + FC_SC;
    float* shs = scs + HID;
    int tid = threadIdx.x, lane = tid & 31, warp = tid >> 5;
    int g = lane >> 2, tg = lane & 3;

    if (tid < HID) {
        float inv_n = 1.f / (float)NN;
        float mu = g_sum[2 * HID + tid] * inv_n;
        float var = g_sumsq[2 * HID + tid] * inv_n - mu * mu;
        float sc = gam[tid] * rsqrtf(var + BN_EPS);
        scs[tid] = sc;
        shs[tid] = bet[tid] - mu * sc;
    }
    for (int i = tid; i < FC_WFRAG_F4; i += 256) {
        int li = i & 31, cg = (i >> 5) & 7, ks = i >> 8;
        int c = cg * 8 + (li >> 2);
        int k = ks * 8 + (li & 3);
        float v0 = W[k * OUTC + c];
        float v1 = W[(k + 4) * OUTC + c];
        unsigned int h0, l0, h1, l1;
        tf32_split(v0, h0, l0);
        tf32_split(v1, h1, l1);
        float4 f;
        f.x = __uint_as_float(h0); f.y = __uint_as_float(h1);
        f.z = __uint_as_float(l0); f.w = __uint_as_float(l1);
        Wfrag[i] = f;
    }

    int wrow = (warp & 3) * 16;
    int wcol = (warp >> 2) * 32;
    int ntbase = (warp >> 2) * 4;
    float bcx[4], bcy[4];
#pragma unroll
    for (int nt = 0; nt < 4; nt++) {
        int c = wcol + nt * 8 + 2 * tg;
        bcx[nt] = __ldg(&b[c]);
        bcy[nt] = __ldg(&b[c + 1]);
    }
    __syncthreads();

    for (int rb = blockIdx.x * 64; rb < NN; rb += FC_GRID * 64) {
        __syncthreads();
        for (int i = tid; i < 64 * 32; i += 256) {
            int row = i >> 5, t4 = i & 31;
            int gr = rb + row;
            float4 v = (gr < NN) ? ((const float4*)g_agg)[(size_t)gr * 32 + t4]
                                 : make_float4(0.f, 0.f, 0.f, 0.f);
            int k = t4 * 4;
            v.x = fmaxf(fmaf(v.x, scs[k + 0], shs[k + 0]), 0.f);
            v.y = fmaxf(fmaf(v.y, scs[k + 1], shs[k + 1]), 0.f);
            v.z = fmaxf(fmaf(v.z, scs[k + 2], shs[k + 2]), 0.f);
            v.w = fmaxf(fmaf(v.w, scs[k + 3], shs[k + 3]), 0.f);
            uint4 hi, lo;
            tf32_split(v.x, hi.x, lo.x);
            tf32_split(v.y, hi.y, lo.y);
            tf32_split(v.z, hi.z, lo.z);
            tf32_split(v.w, hi.w, lo.w);
            *(uint4*)(xhi + row * FC_LDX + t4 * 4) = hi;
            *(uint4*)(xlo + row * FC_LDX + t4 * 4) = lo;
        }
        __syncthreads();

        float d[4][4];
#pragma unroll
        for (int nt = 0; nt < 4; nt++) { d[nt][0]=0.f; d[nt][1]=0.f; d[nt][2]=0.f; d[nt][3]=0.f; }

#pragma unroll
        for (int ks = 0; ks < 16; ks++) {
            int k0 = ks * 8;
            unsigned int ah0 = __float_as_uint(xhi[(wrow + g) * FC_LDX + k0 + tg]);
            unsigned int ah1 = __float_as_uint(xhi[(wrow + g + 8) * FC_LDX + k0 + tg]);
            unsigned int ah2 = __float_as_uint(xhi[(wrow + g) * FC_LDX + k0 + tg + 4]);
            unsigned int ah3 = __float_as_uint(xhi[(wrow + g + 8) * FC_LDX + k0 + tg + 4]);
            unsigned int al0 = __float_as_uint(xlo[(wrow + g) * FC_LDX + k0 + tg]);
            unsigned int al1 = __float_as_uint(xlo[(wrow + g + 8) * FC_LDX + k0 + tg]);
            unsigned int al2 = __float_as_uint(xlo[(wrow + g) * FC_LDX + k0 + tg + 4]);
            unsigned int al3 = __float_as_uint(xlo[(wrow + g + 8) * FC_LDX + k0 + tg + 4]);
            const float4* wf = Wfrag + (ks * 8 + ntbase) * 32 + lane;
#pragma unroll
            for (int nt = 0; nt < 4; nt++) {
                float4 bf = wf[nt * 32];
                unsigned int bh0 = __float_as_uint(bf.x);
                unsigned int bh1 = __float_as_uint(bf.y);
                unsigned int bl0 = __float_as_uint(bf.z);
                unsigned int bl1 = __float_as_uint(bf.w);
#define MMA(A0,A1,A2,A3,B0,B1) \
                asm volatile( \
                    "mma.sync.aligned.m16n8k8.row.col.f32.tf32.tf32.f32 " \
                    "{%0,%1,%2,%3}, {%4,%5,%6,%7}, {%8,%9}, {%0,%1,%2,%3};" \
                    : "+f"(d[nt][0]), "+f"(d[nt][1]), "+f"(d[nt][2]), "+f"(d[nt][3]) \
                    : "r"(A0), "r"(A1), "r"(A2), "r"(A3), "r"(B0), "r"(B1));
                MMA(ah0, ah1, ah2, ah3, bh0, bh1)
                MMA(ah0, ah1, ah2, ah3, bl0, bl1)
                MMA(al0, al1, al2, al3, bh0, bh1)
#undef MMA
            }
        }

        int r0 = rb + wrow + g;
        int r1 = r0 + 8;
#pragma unroll
        for (int nt = 0; nt < 4; nt++) {
            int c = wcol + nt * 8 + 2 * tg;
            if (r0 < NN)
                *(float2*)(out + (size_t)r0 * OUTC + c) =
                    make_float2(d[nt][0] + bcx[nt], d[nt][1] + bcy[nt]);
            if (r1 < NN)
                *(float2*)(out + (size_t)r1 * OUTC + c) =
                    make_float2(d[nt][2] + bcx[nt], d[nt][3] + bcy[nt]);
        }
    }
}

// ---------------- launch ----------------
extern "C" void kernel_launch(void* const* d_in, const int* in_sizes, int n_in,
                              void* d_out, int out_size) {
    const float* h   = (const float*)d_in[0];
    const int*   src = (const int*)d_in[1];
    const int*   dst = (const int*)d_in[2];
    const float* w0  = (const float*)d_in[3];
    const float* b0  = (const float*)d_in[4];
    const float* w1  = (const float*)d_in[5];
    const float* b1  = (const float*)d_in[6];
    const float* w2  = (const float*)d_in[7];
    const float* b2  = (const float*)d_in[8];
    const float* g0  = (const float*)d_in[9];
    const float* bt0 = (const float*)d_in[10];
    const float* g1  = (const float*)d_in[11];
    const float* bt1 = (const float*)d_in[12];
    const float* g2  = (const float*)d_in[13];
    const float* bt2 = (const float*)d_in[14];
    const float* wfc = (const float*)d_in[15];
    const float* bfc = (const float*)d_in[16];
    float* out = (float*)d_out;

    cudaFuncSetAttribute(k_gemm_tf32, cudaFuncAttributeMaxDynamicSharedMemorySize, GT_SMEM);
    cudaFuncSetAttribute(k_gemm_l0_tf32, cudaFuncAttributeMaxDynamicSharedMemorySize, L0_SMEM);
    cudaFuncSetAttribute(k_fc_tf32, cudaFuncAttributeMaxDynamicSharedMemorySize, FC_SMEM);

    // graph prep
    k_zero_deg<<<(NN + 255) / 256, 256>>>();
    k_degrees<<<(NE / 4 + 255) / 256, 256>>>(src, dst);
    k_nodeprep_alloc<<<(NN + 255) / 256, 256>>>(h, out);
    k_fill<<<(NE / 4 + 255) / 256, 256>>>(src, dst);

    // ---- layer 0 (26 -> 128), stats -> slot 0, out fp16 ----
    k_gather26<<<(NN * 32 + 255) / 256, 256>>>();
    k_gemm_l0_tf32<<<L0_GRID, 256, L0_SMEM>>>(w0, b0);

    // ---- layers 1, 2 (128 -> 128), stats -> slots 1, 2 ----
    // layer 1 out: fp16 g_x16; layer 2 out: fp32 in-place g_agg (FC input)
    const float* Ws[2]  = {w1, w2};
    const float* bs[2]  = {b1, b2};
    const float* gs[2]  = {g0, g1};
    const float* bts[2] = {bt0, bt1};
    for (int l = 0; l < 2; l++) {
        k_prescale<<<(NN * (HID / 4) + 255) / 256, 256>>>(gs[l], bts[l], l);
        k_gather128<<<(NN * 32 + 255) / 256, 256>>>();
        k_gemm_tf32<<<GT_GRID, 256, GT_SMEM>>>(Ws[l], bs[l], l + 1, l == 1 ? 1 : 0);
    }

    // ---- final FC (128 -> 64), fp32 input from g_agg, BN2+ReLU fused ----
    k_fc_tf32<<<FC_GRID, 256, FC_SMEM>>>(wfc, bfc, g2, bt2, out);
}

// round 17
// speedup vs baseline: 1.1084x; 1.0008x over previous
#include <cuda_runtime.h>
#include <cuda_fp16.h>

#define NN   100000
#define NE   1600000
#define INC  26
#define HID  128
#define OUTC 64
#define BN_EPS 1e-5f
#define OUT_ELEMS (NN * OUTC)
#define CSR_CAP (NE + 4 * NN)

// ---------------- device scratch ----------------
__device__ __half g_x16[NN * HID];  // raw layer-0/1 outputs, fp16 (prescale input)
__device__ __half g_xh[NN * HID];   // pre-scaled activations, fp16 (gather input)
__device__ __half g_h16[NN * 32];   // layer-0 messages: half(h * norm_src), padded to 32ch
__device__ float  g_agg[NN * HID];  // gather accumulator; layer-2 output written fp32 in place
__device__ float  g_norm_src[NN];
__device__ float  g_norm_dst[NN];
__device__ int    g_deg_out_i[NN];
__device__ int    g_deg_in_i[NN];
__device__ int    g_rowptr[NN];
__device__ int    g_cursor[NN];
__device__ int    g_csr_src[CSR_CAP];
__device__ int    g_total;
__device__ float  g_sum[3 * HID];
__device__ float  g_sumsq[3 * HID];

__constant__ float c_wtable[26] = {
    0.7f,0.9f,0.7f,0.9f,0.3f,0.7f,0.3f,0.9f,0.3f,0.3f,0.9f,0.7f,0.1f,
    0.9f,0.5f,0.9f,0.5f,0.5f,0.1f,0.3f,0.7f,0.9f,0.9f,0.9f,0.9f,0.9f};

__device__ __forceinline__ void tf32_split(float v, unsigned int& hi, unsigned int& lo) {
    asm("cvt.rna.tf32.f32 %0, %1;" : "=r"(hi) : "f"(v));
    float rem = v - __uint_as_float(hi);
    asm("cvt.rna.tf32.f32 %0, %1;" : "=r"(lo) : "f"(rem));
}

// ---------------- prep kernels ----------------
__global__ void k_zero_deg() {
    int n = blockIdx.x * blockDim.x + threadIdx.x;
    if (n < NN) { g_deg_out_i[n] = 0; g_deg_in_i[n] = 0; }
    if (n < 3 * HID) { g_sum[n] = 0.f; g_sumsq[n] = 0.f; }
    if (n == 0) g_total = 0;
}

__global__ void k_degrees(const int* __restrict__ src, const int* __restrict__ dst) {
    int t = blockIdx.x * blockDim.x + threadIdx.x;
    if (t >= NE / 4) return;
    int4 s = ((const int4*)src)[t];
    int4 d = ((const int4*)dst)[t];
    atomicAdd(&g_deg_out_i[s.x], 1);
    atomicAdd(&g_deg_out_i[s.y], 1);
    atomicAdd(&g_deg_out_i[s.z], 1);
    atomicAdd(&g_deg_out_i[s.w], 1);
    atomicAdd(&g_deg_in_i[d.x], 1);
    atomicAdd(&g_deg_in_i[d.y], 1);
    atomicAdd(&g_deg_in_i[d.z], 1);
    atomicAdd(&g_deg_in_i[d.w], 1);
}

__global__ void k_nodeprep_alloc(const float* __restrict__ h, float* __restrict__ out) {
    int n = blockIdx.x * blockDim.x + threadIdx.x;
    int lane = threadIdx.x & 31;

    int dpad = 0, deg_in = 0;
    if (n < NN) {
        deg_in = g_deg_in_i[n];
        dpad = (deg_in + 3) & ~3;
    }
    int incl = dpad;
#pragma unroll
    for (int o = 1; o < 32; o <<= 1) {
        int t = __shfl_up_sync(0xffffffff, incl, o);
        if (lane >= o) incl += t;
    }
    int wtotal = __shfl_sync(0xffffffff, incl, 31);
    int base = 0;
    if (lane == 0) base = atomicAdd(&g_total, wtotal);
    base = __shfl_sync(0xffffffff, base, 0);
    if (n >= NN) return;
    int pos = base + incl - dpad;
    g_rowptr[n] = pos;
    g_cursor[n] = pos;

    const float* hr = h + (size_t)n * INC;
    float hv[INC];
    float best = -1e30f;
    int bi = 0;
#pragma unroll
    for (int c = 0; c < INC; c++) {
        float v = hr[c];
        hv[c] = v;
        if (v > best) { best = v; bi = c; }
    }
    out[OUT_ELEMS + n] = c_wtable[bi];
    float ns = rsqrtf(fmaxf((float)g_deg_out_i[n], 1.f));
    g_norm_src[n] = ns;
    g_norm_dst[n] = rsqrtf(fmaxf((float)deg_in, 1.f));
    unsigned int* dsth = (unsigned int*)g_h16 + (size_t)n * 16;
#pragma unroll
    for (int j = 0; j < 13; j++) {
        __half2 p = __floats2half2_rn(hv[2 * j] * ns, hv[2 * j + 1] * ns);
        dsth[j] = *(unsigned int*)&p;
    }
    dsth[13] = 0; dsth[14] = 0; dsth[15] = 0;
}

__global__ void k_fill(const int* __restrict__ src, const int* __restrict__ dst) {
    int t = blockIdx.x * blockDim.x + threadIdx.x;
    if (t >= NE / 4) return;
    int4 s = ((const int4*)src)[t];
    int4 d = ((const int4*)dst)[t];
    g_csr_src[atomicAdd(&g_cursor[d.x], 1)] = s.x;
    g_csr_src[atomicAdd(&g_cursor[d.y], 1)] = s.y;
    g_csr_src[atomicAdd(&g_cursor[d.z], 1)] = s.z;
    g_csr_src[atomicAdd(&g_cursor[d.w], 1)] = s.w;
}

// ---------------- layer-0 gather: half-warp per node, MLP=8, no reduce ----------------
// node's 32 channels = 16 uints (half2 pairs); 16 lanes cover the row, each lane
// accumulates its 2 channels over all edges.
__global__ void k_gather26() {
    int gid = blockIdx.x * blockDim.x + threadIdx.x;
    int n = gid >> 4;          // half-warp per node
    int sub = gid & 15;        // uint index within row (2 channels)
    if (n >= NN) return;
    const int* cs = g_csr_src + g_rowptr[n];
    int cnt = g_deg_in_i[n];
    const unsigned int* xh = (const unsigned int*)g_h16;
    float2 acc = make_float2(0.f, 0.f);
    float2 a;
#define ACC1(P) \
    a = __half22float2(*(__half2*)&P); acc.x += a.x; acc.y += a.y;
    int i = 0;
    for (; i + 8 <= cnt; i += 8) {
        int4 ia = *(const int4*)(cs + i);
        int4 ib = *(const int4*)(cs + i + 4);
        unsigned int p0 = __ldg(xh + (size_t)ia.x * 16 + sub);
        unsigned int p1 = __ldg(xh + (size_t)ia.y * 16 + sub);
        unsigned int p2 = __ldg(xh + (size_t)ia.z * 16 + sub);
        unsigned int p3 = __ldg(xh + (size_t)ia.w * 16 + sub);
        unsigned int p4 = __ldg(xh + (size_t)ib.x * 16 + sub);
        unsigned int p5 = __ldg(xh + (size_t)ib.y * 16 + sub);
        unsigned int p6 = __ldg(xh + (size_t)ib.z * 16 + sub);
        unsigned int p7 = __ldg(xh + (size_t)ib.w * 16 + sub);
        ACC1(p0) ACC1(p1) ACC1(p2) ACC1(p3) ACC1(p4) ACC1(p5) ACC1(p6) ACC1(p7)
    }
    for (; i + 4 <= cnt; i += 4) {
        int4 ia = *(const int4*)(cs + i);
        unsigned int p0 = __ldg(xh + (size_t)ia.x * 16 + sub);
        unsigned int p1 = __ldg(xh + (size_t)ia.y * 16 + sub);
        unsigned int p2 = __ldg(xh + (size_t)ia.z * 16 + sub);
        unsigned int p3 = __ldg(xh + (size_t)ia.w * 16 + sub);
        ACC1(p0) ACC1(p1) ACC1(p2) ACC1(p3)
    }
    for (; i < cnt; i++) {
        int s = cs[i];
        unsigned int p = __ldg(xh + (size_t)s * 16 + sub);
        ACC1(p)
    }
#undef ACC1
    ((float2*)(g_agg + (size_t)n * 32))[sub] = acc;
}

// pre-scale: BN scale/shift from stats slot, then g_xh <- half(relu(bn(g_x16)) * norm_src)
__global__ void k_prescale(const float* __restrict__ g, const float* __restrict__ bt,
                           int slot) {
    __shared__ float scs[HID], shs[HID];
    int tid = threadIdx.x;
    if (tid < HID) {
        float inv_n = 1.f / (float)NN;
        float mu = g_sum[slot * HID + tid] * inv_n;
        float var = g_sumsq[slot * HID + tid] * inv_n - mu * mu;
        float sc = g[tid] * rsqrtf(var + BN_EPS);
        scs[tid] = sc;
        shs[tid] = bt[tid] - mu * sc;
    }
    __syncthreads();
    int i = blockIdx.x * blockDim.x + threadIdx.x;
    if (i >= NN * (HID / 4)) return;
    int lane = i & 31;
    int row = i >> 5;
    float4 sc = *(const float4*)(scs + lane * 4);
    float4 sh = *(const float4*)(shs + lane * 4);
    float ns = g_norm_src[row];
    uint2 p = ((const uint2*)g_x16)[i];
    float2 v01 = __half22float2(*(__half2*)&p.x);
    float2 v23 = __half22float2(*(__half2*)&p.y);
    float2 lo = make_float2(fmaxf(fmaf(v01.x, sc.x, sh.x), 0.f) * ns,
                            fmaxf(fmaf(v01.y, sc.y, sh.y), 0.f) * ns);
    float2 hi = make_float2(fmaxf(fmaf(v23.x, sc.z, sh.z), 0.f) * ns,
                            fmaxf(fmaf(v23.y, sc.w, sh.w), 0.f) * ns);
    __half2 h0 = __float22half2_rn(lo);
    __half2 h1 = __float22half2_rn(hi);
    uint2 packed;
    packed.x = *(unsigned int*)&h0;
    packed.y = *(unsigned int*)&h1;
    ((uint2*)g_xh)[i] = packed;
}

// pure-sum gather, fp16 rows, fp32 accumulation, warp-per-node, MLP=16
__global__ void k_gather128() {
    int gid = blockIdx.x * blockDim.x + threadIdx.x;
    int n = gid >> 5;
    int lane = gid & 31;
    if (n >= NN) return;
    const int* cs = g_csr_src + g_rowptr[n];
    int cnt = g_deg_in_i[n];
    float4 acc = make_float4(0.f, 0.f, 0.f, 0.f);
    const uint2* xh = (const uint2*)g_xh;
    float2 a, bb;
#define ACC(P) \
        a = __half22float2(*(__half2*)&P.x); bb = __half22float2(*(__half2*)&P.y); \
        acc.x += a.x; acc.y += a.y; acc.z += bb.x; acc.w += bb.y;
    int i = 0;
    for (; i + 16 <= cnt; i += 16) {
        int4 ia = *(const int4*)(cs + i);
        int4 ib = *(const int4*)(cs + i + 4);
        int4 ic = *(const int4*)(cs + i + 8);
        int4 id = *(const int4*)(cs + i + 12);
        uint2 p0 = __ldg(xh + (size_t)ia.x * 32 + lane);
        uint2 p1 = __ldg(xh + (size_t)ia.y * 32 + lane);
        uint2 p2 = __ldg(xh + (size_t)ia.z * 32 + lane);
        uint2 p3 = __ldg(xh + (size_t)ia.w * 32 + lane);
        uint2 p4 = __ldg(xh + (size_t)ib.x * 32 + lane);
        uint2 p5 = __ldg(xh + (size_t)ib.y * 32 + lane);
        uint2 p6 = __ldg(xh + (size_t)ib.z * 32 + lane);
        uint2 p7 = __ldg(xh + (size_t)ib.w * 32 + lane);
        uint2 p8 = __ldg(xh + (size_t)ic.x * 32 + lane);
        uint2 p9 = __ldg(xh + (size_t)ic.y * 32 + lane);
        uint2 pa = __ldg(xh + (size_t)ic.z * 32 + lane);
        uint2 pb = __ldg(xh + (size_t)ic.w * 32 + lane);
        uint2 pc = __ldg(xh + (size_t)id.x * 32 + lane);
        uint2 pd = __ldg(xh + (size_t)id.y * 32 + lane);
        uint2 pe = __ldg(xh + (size_t)id.z * 32 + lane);
        uint2 pf = __ldg(xh + (size_t)id.w * 32 + lane);
        ACC(p0) ACC(p1) ACC(p2) ACC(p3) ACC(p4) ACC(p5) ACC(p6) ACC(p7)
        ACC(p8) ACC(p9) ACC(pa) ACC(pb) ACC(pc) ACC(pd) ACC(pe) ACC(pf)
    }
    for (; i + 4 <= cnt; i += 4) {
        int4 ia = *(const int4*)(cs + i);
        uint2 p0 = __ldg(xh + (size_t)ia.x * 32 + lane);
        uint2 p1 = __ldg(xh + (size_t)ia.y * 32 + lane);
        uint2 p2 = __ldg(xh + (size_t)ia.z * 32 + lane);
        uint2 p3 = __ldg(xh + (size_t)ia.w * 32 + lane);
        ACC(p0) ACC(p1) ACC(p2) ACC(p3)
    }
    for (; i < cnt; i++) {
        int s0 = cs[i];
        uint2 p0 = __ldg(xh + (size_t)s0 * 32 + lane);
        ACC(p0)
    }
#undef ACC
    ((float4*)(g_agg + (size_t)n * HID))[lane] = acc;
}

// ============ GEMMs: 3xTF32 with fragment-layout W ============

// ---- layer-0 GEMM: K=32 (4 ks), 128 cols (16 groups), out fp16 ----
#define L0_WFRAG_F4 (4 * 16 * 32)
#define L0_LDX 132
#define L0_XHI (L0_WFRAG_F4 * 4)
#define L0_XLO (L0_WFRAG_F4 * 4 + 64 * L0_LDX)
#define L0_SMEM ((L0_WFRAG_F4 * 4 + 2 * 64 * L0_LDX) * 4)
#define L0_GRID 148
__global__ void __launch_bounds__(256, 1) k_gemm_l0_tf32(const float* __restrict__ W,
                                                         const float* __restrict__ b) {
    extern __shared__ float sm[];
    float4* Wfrag = (float4*)sm;
    float* xhi = sm + L0_XHI;
    float* xlo = sm + L0_XLO;
    int tid = threadIdx.x, lane = tid & 31, warp = tid >> 5;
    int g = lane >> 2, tg = lane & 3;

    for (int i = tid; i < L0_WFRAG_F4; i += 256) {
        int li = i & 31, cg = (i >> 5) & 15, ks = i >> 9;
        int c = cg * 8 + (li >> 2);
        int k = ks * 8 + (li & 3);
        float v0 = (k < INC) ? W[k * HID + c] : 0.f;
        float v1 = (k + 4 < INC) ? W[(k + 4) * HID + c] : 0.f;
        unsigned int h0, l0, h1, l1;
        tf32_split(v0, h0, l0);
        tf32_split(v1, h1, l1);
        float4 f;
        f.x = __uint_as_float(h0); f.y = __uint_as_float(h1);
        f.z = __uint_as_float(l0); f.w = __uint_as_float(l1);
        Wfrag[i] = f;
    }

    int wrow = (warp & 3) * 16;
    int wcol = (warp >> 2) * 64;
    int ntbase = (warp >> 2) * 8;
    float bcx[8], bcy[8];
#pragma unroll
    for (int nt = 0; nt < 8; nt++) {
        int c = wcol + nt * 8 + 2 * tg;
        bcx[nt] = __ldg(&b[c]);
        bcy[nt] = __ldg(&b[c + 1]);
    }
    float scol[16], qcol[16];
#pragma unroll
    for (int t = 0; t < 16; t++) { scol[t] = 0.f; qcol[t] = 0.f; }

    for (int rb = blockIdx.x * 64; rb < NN; rb += L0_GRID * 64) {
        __syncthreads();
        for (int i = tid; i < 64 * 8; i += 256) {
            int row = i >> 3, t4 = i & 7;
            int gr = rb + row;
            float4 v = (gr < NN) ? ((const float4*)g_agg)[(size_t)gr * 8 + t4]
                                 : make_float4(0.f, 0.f, 0.f, 0.f);
            uint4 hi, lo;
            tf32_split(v.x, hi.x, lo.x);
            tf32_split(v.y, hi.y, lo.y);
            tf32_split(v.z, hi.z, lo.z);
            tf32_split(v.w, hi.w, lo.w);
            *(uint4*)(xhi + row * L0_LDX + t4 * 4) = hi;
            *(uint4*)(xlo + row * L0_LDX + t4 * 4) = lo;
        }
        __syncthreads();

        float d[8][4];
#pragma unroll
        for (int nt = 0; nt < 8; nt++) { d[nt][0]=0.f; d[nt][1]=0.f; d[nt][2]=0.f; d[nt][3]=0.f; }

#pragma unroll
        for (int ks = 0; ks < 4; ks++) {
            int k0 = ks * 8;
            unsigned int ah0 = __float_as_uint(xhi[(wrow + g) * L0_LDX + k0 + tg]);
            unsigned int ah1 = __float_as_uint(xhi[(wrow + g + 8) * L0_LDX + k0 + tg]);
            unsigned int ah2 = __float_as_uint(xhi[(wrow + g) * L0_LDX + k0 + tg + 4]);
            unsigned int ah3 = __float_as_uint(xhi[(wrow + g + 8) * L0_LDX + k0 + tg + 4]);
            unsigned int al0 = __float_as_uint(xlo[(wrow + g) * L0_LDX + k0 + tg]);
            unsigned int al1 = __float_as_uint(xlo[(wrow + g + 8) * L0_LDX + k0 + tg]);
            unsigned int al2 = __float_as_uint(xlo[(wrow + g) * L0_LDX + k0 + tg + 4]);
            unsigned int al3 = __float_as_uint(xlo[(wrow + g + 8) * L0_LDX + k0 + tg + 4]);
            const float4* wf = Wfrag + (ks * 16 + ntbase) * 32 + lane;
#pragma unroll
            for (int nt = 0; nt < 8; nt++) {
                float4 bf = wf[nt * 32];
                unsigned int bh0 = __float_as_uint(bf.x);
                unsigned int bh1 = __float_as_uint(bf.y);
                unsigned int bl0 = __float_as_uint(bf.z);
                unsigned int bl1 = __float_as_uint(bf.w);
#define MMA(A0,A1,A2,A3,B0,B1) \
                asm volatile( \
                    "mma.sync.aligned.m16n8k8.row.col.f32.tf32.tf32.f32 " \
                    "{%0,%1,%2,%3}, {%4,%5,%6,%7}, {%8,%9}, {%0,%1,%2,%3};" \
                    : "+f"(d[nt][0]), "+f"(d[nt][1]), "+f"(d[nt][2]), "+f"(d[nt][3]) \
                    : "r"(A0), "r"(A1), "r"(A2), "r"(A3), "r"(B0), "r"(B1));
                MMA(ah0, ah1, ah2, ah3, bh0, bh1)
                MMA(ah0, ah1, ah2, ah3, bl0, bl1)
                MMA(al0, al1, al2, al3, bh0, bh1)
#undef MMA
            }
        }

        int r0 = rb + wrow + g;
        int r1 = r0 + 8;
        bool v0 = r0 < NN, v1 = r1 < NN;
        float nd0 = v0 ? g_norm_dst[r0] : 0.f;
        float nd1 = v1 ? g_norm_dst[r1] : 0.f;
#pragma unroll
        for (int nt = 0; nt < 8; nt++) {
            int c = wcol + nt * 8 + 2 * tg;
            if (v0) {
                float yx = d[nt][0] * nd0 + bcx[nt];
                float yy = d[nt][1] * nd0 + bcy[nt];
                __half2 hp = __floats2half2_rn(yx, yy);
                *(unsigned int*)(g_x16 + (size_t)r0 * HID + c) = *(unsigned int*)&hp;
                scol[nt * 2] += yx;     qcol[nt * 2]     = fmaf(yx, yx, qcol[nt * 2]);
                scol[nt * 2 + 1] += yy; qcol[nt * 2 + 1] = fmaf(yy, yy, qcol[nt * 2 + 1]);
            }
            if (v1) {
                float yx = d[nt][2] * nd1 + bcx[nt];
                float yy = d[nt][3] * nd1 + bcy[nt];
                __half2 hp = __floats2half2_rn(yx, yy);
                *(unsigned int*)(g_x16 + (size_t)r1 * HID + c) = *(unsigned int*)&hp;
                scol[nt * 2] += yx;     qcol[nt * 2]     = fmaf(yx, yx, qcol[nt * 2]);
                scol[nt * 2 + 1] += yy; qcol[nt * 2 + 1] = fmaf(yy, yy, qcol[nt * 2 + 1]);
            }
        }
    }

#pragma unroll
    for (int t = 0; t < 16; t++) {
        scol[t] += __shfl_xor_sync(0xffffffff, scol[t], 4);
        scol[t] += __shfl_xor_sync(0xffffffff, scol[t], 8);
        scol[t] += __shfl_xor_sync(0xffffffff, scol[t], 16);
        qcol[t] += __shfl_xor_sync(0xffffffff, qcol[t], 4);
        qcol[t] += __shfl_xor_sync(0xffffffff, qcol[t], 8);
        qcol[t] += __shfl_xor_sync(0xffffffff, qcol[t], 16);
    }
    if (g == 0) {
#pragma unroll
        for (int nt = 0; nt < 8; nt++) {
            int c = wcol + nt * 8 + 2 * tg;
            atomicAdd(&g_sum[c],     scol[nt * 2]);
            atomicAdd(&g_sum[c + 1], scol[nt * 2 + 1]);
            atomicAdd(&g_sumsq[c],     qcol[nt * 2]);
            atomicAdd(&g_sumsq[c + 1], qcol[nt * 2 + 1]);
        }
    }
}

// ---- hidden GEMM: K=128 (16 ks), 128 cols; writeFp32 selects epilogue target ----
#define GT_WFRAG_F4 (16 * 16 * 32)
#define GT_LDX 132
#define GT_XHI (GT_WFRAG_F4 * 4)
#define GT_XLO (GT_WFRAG_F4 * 4 + 64 * GT_LDX)
#define GT_SMEM ((GT_WFRAG_F4 * 4 + 2 * 64 * GT_LDX) * 4)
#define GT_GRID 148
__global__ void __launch_bounds__(256, 1) k_gemm_tf32(const float* __restrict__ W,
                                                      const float* __restrict__ b,
                                                      int slot, int writeFp32) {
    extern __shared__ float sm[];
    float4* Wfrag = (float4*)sm;
    float* xhi = sm + GT_XHI;
    float* xlo = sm + GT_XLO;
    int tid = threadIdx.x, lane = tid & 31, warp = tid >> 5;
    int g = lane >> 2, tg = lane & 3;

    for (int i = tid; i < GT_WFRAG_F4; i += 256) {
        int li = i & 31, cg = (i >> 5) & 15, ks = i >> 9;
        int c = cg * 8 + (li >> 2);
        int k = ks * 8 + (li & 3);
        float v0 = W[k * HID + c];
        float v1 = W[(k + 4) * HID + c];
        unsigned int h0, l0, h1, l1;
        tf32_split(v0, h0, l0);
        tf32_split(v1, h1, l1);
        float4 f;
        f.x = __uint_as_float(h0); f.y = __uint_as_float(h1);
        f.z = __uint_as_float(l0); f.w = __uint_as_float(l1);
        Wfrag[i] = f;
    }

    int wrow = (warp & 3) * 16;
    int wcol = (warp >> 2) * 64;
    int ntbase = (warp >> 2) * 8;
    float bcx[8], bcy[8];
#pragma unroll
    for (int nt = 0; nt < 8; nt++) {
        int c = wcol + nt * 8 + 2 * tg;
        bcx[nt] = __ldg(&b[c]);
        bcy[nt] = __ldg(&b[c + 1]);
    }
    float scol[16], qcol[16];
#pragma unroll
    for (int t = 0; t < 16; t++) { scol[t] = 0.f; qcol[t] = 0.f; }

    for (int rb = blockIdx.x * 64; rb < NN; rb += GT_GRID * 64) {
        __syncthreads();
        for (int i = tid; i < 64 * 32; i += 256) {
            int row = i >> 5, t4 = i & 31;
            int gr = rb + row;
            float4 v = (gr < NN) ? ((const float4*)g_agg)[(size_t)gr * 32 + t4]
                                 : make_float4(0.f, 0.f, 0.f, 0.f);
            uint4 hi, lo;
            tf32_split(v.x, hi.x, lo.x);
            tf32_split(v.y, hi.y, lo.y);
            tf32_split(v.z, hi.z, lo.z);
            tf32_split(v.w, hi.w, lo.w);
            *(uint4*)(xhi + row * GT_LDX + t4 * 4) = hi;
            *(uint4*)(xlo + row * GT_LDX + t4 * 4) = lo;
        }
        __syncthreads();

        float d[8][4];
#pragma unroll
        for (int nt = 0; nt < 8; nt++) { d[nt][0]=0.f; d[nt][1]=0.f; d[nt][2]=0.f; d[nt][3]=0.f; }

#pragma unroll
        for (int ks = 0; ks < 16; ks++) {
            int k0 = ks * 8;
            unsigned int ah0 = __float_as_uint(xhi[(wrow + g) * GT_LDX + k0 + tg]);
            unsigned int ah1 = __float_as_uint(xhi[(wrow + g + 8) * GT_LDX + k0 + tg]);
            unsigned int ah2 = __float_as_uint(xhi[(wrow + g) * GT_LDX + k0 + tg + 4]);
            unsigned int ah3 = __float_as_uint(xhi[(wrow + g + 8) * GT_LDX + k0 + tg + 4]);
            unsigned int al0 = __float_as_uint(xlo[(wrow + g) * GT_LDX + k0 + tg]);
            unsigned int al1 = __float_as_uint(xlo[(wrow + g + 8) * GT_LDX + k0 + tg]);
            unsigned int al2 = __float_as_uint(xlo[(wrow + g) * GT_LDX + k0 + tg + 4]);
            unsigned int al3 = __float_as_uint(xlo[(wrow + g + 8) * GT_LDX + k0 + tg + 4]);
            const float4* wf = Wfrag + (ks * 16 + ntbase) * 32 + lane;
#pragma unroll
            for (int nt = 0; nt < 8; nt++) {
                float4 bf = wf[nt * 32];
                unsigned int bh0 = __float_as_uint(bf.x);
                unsigned int bh1 = __float_as_uint(bf.y);
                unsigned int bl0 = __float_as_uint(bf.z);
                unsigned int bl1 = __float_as_uint(bf.w);
#define MMA(A0,A1,A2,A3,B0,B1) \
                asm volatile( \
                    "mma.sync.aligned.m16n8k8.row.col.f32.tf32.tf32.f32 " \
                    "{%0,%1,%2,%3}, {%4,%5,%6,%7}, {%8,%9}, {%0,%1,%2,%3};" \
                    : "+f"(d[nt][0]), "+f"(d[nt][1]), "+f"(d[nt][2]), "+f"(d[nt][3]) \
                    : "r"(A0), "r"(A1), "r"(A2), "r"(A3), "r"(B0), "r"(B1));
                MMA(ah0, ah1, ah2, ah3, bh0, bh1)
                MMA(ah0, ah1, ah2, ah3, bl0, bl1)
                MMA(al0, al1, al2, al3, bh0, bh1)
#undef MMA
            }
        }

        int r0 = rb + wrow + g;
        int r1 = r0 + 8;
        bool v0 = r0 < NN, v1 = r1 < NN;
        float nd0 = v0 ? g_norm_dst[r0] : 0.f;
        float nd1 = v1 ? g_norm_dst[r1] : 0.f;
#pragma unroll
        for (int nt = 0; nt < 8; nt++) {
            int c = wcol + nt * 8 + 2 * tg;
            if (v0) {
                float yx = d[nt][0] * nd0 + bcx[nt];
                float yy = d[nt][1] * nd0 + bcy[nt];
                if (writeFp32) {
                    *(float2*)(g_agg + (size_t)r0 * HID + c) = make_float2(yx, yy);
                } else {
                    __half2 hp = __floats2half2_rn(yx, yy);
                    *(unsigned int*)(g_x16 + (size_t)r0 * HID + c) = *(unsigned int*)&hp;
                }
                scol[nt * 2] += yx;     qcol[nt * 2]     = fmaf(yx, yx, qcol[nt * 2]);
                scol[nt * 2 + 1] += yy; qcol[nt * 2 + 1] = fmaf(yy, yy, qcol[nt * 2 + 1]);
            }
            if (v1) {
                float yx = d[nt][2] * nd1 + bcx[nt];
                float yy = d[nt][3] * nd1 + bcy[nt];
                if (writeFp32) {
                    *(float2*)(g_agg + (size_t)r1 * HID + c) = make_float2(yx, yy);
                } else {
                    __half2 hp = __floats2half2_rn(yx, yy);
                    *(unsigned int*)(g_x16 + (size_t)r1 * HID + c) = *(unsigned int*)&hp;
                }
                scol[nt * 2] += yx;     qcol[nt * 2]     = fmaf(yx, yx, qcol[nt * 2]);
                scol[nt * 2 + 1] += yy; qcol[nt * 2 + 1] = fmaf(yy, yy, qcol[nt * 2 + 1]);
            }
        }
    }

#pragma unroll
    for (int t = 0; t < 16; t++) {
        scol[t] += __shfl_xor_sync(0xffffffff, scol[t], 4);
        scol[t] += __shfl_xor_sync(0xffffffff, scol[t], 8);
        scol[t] += __shfl_xor_sync(0xffffffff, scol[t], 16);
        qcol[t] += __shfl_xor_sync(0xffffffff, qcol[t], 4);
        qcol[t] += __shfl_xor_sync(0xffffffff, qcol[t], 8);
        qcol[t] += __shfl_xor_sync(0xffffffff, qcol[t], 16);
    }
    if (g == 0) {
        float* gsum = g_sum + slot * HID;
        float* gsq  = g_sumsq + slot * HID;
#pragma unroll
        for (int nt = 0; nt < 8; nt++) {
            int c = wcol + nt * 8 + 2 * tg;
            atomicAdd(&gsum[c],     scol[nt * 2]);
            atomicAdd(&gsum[c + 1], scol[nt * 2 + 1]);
            atomicAdd(&gsq[c],      qcol[nt * 2]);
            atomicAdd(&gsq[c + 1],  qcol[nt * 2 + 1]);
        }
    }
}

// ---- final FC: reads fp32 g_agg; BN2+ReLU fused in staging ----
#define FC_WFRAG_F4 (16 * 8 * 32)
#define FC_LDX 132
#define FC_XHI (FC_WFRAG_F4 * 4)
#define FC_XLO (FC_WFRAG_F4 * 4 + 64 * FC_LDX)
#define FC_SC  (FC_WFRAG_F4 * 4 + 2 * 64 * FC_LDX)
#define FC_SMEM ((FC_WFRAG_F4 * 4 + 2 * 64 * FC_LDX + 2 * HID) * 4)
#define FC_GRID 148
__global__ void __launch_bounds__(256, 1) k_fc_tf32(const float* __restrict__ W,
                                                    const float* __restrict__ b,
                                                    const float* __restrict__ gam,
                                                    const float* __restrict__ bet,
                                                    float* __restrict__ out) {
    extern __shared__ float sm[];
    float4* Wfrag = (float4*)sm;
    float* xhi = sm + FC_XHI;
    float* xlo = sm + FC_XLO;
    float* scs = sm + FC_SC;
    float* shs = scs + HID;
    int tid = threadIdx.x, lane = tid & 31, warp = tid >> 5;
    int g = lane >> 2, tg = lane & 3;

    if (tid < HID) {
        float inv_n = 1.f / (float)NN;
        float mu = g_sum[2 * HID + tid] * inv_n;
        float var = g_sumsq[2 * HID + tid] * inv_n - mu * mu;
        float sc = gam[tid] * rsqrtf(var + BN_EPS);
        scs[tid] = sc;
        shs[tid] = bet[tid] - mu * sc;
    }
    for (int i = tid; i < FC_WFRAG_F4; i += 256) {
        int li = i & 31, cg = (i >> 5) & 7, ks = i >> 8;
        int c = cg * 8 + (li >> 2);
        int k = ks * 8 + (li & 3);
        float v0 = W[k * OUTC + c];
        float v1 = W[(k + 4) * OUTC + c];
        unsigned int h0, l0, h1, l1;
        tf32_split(v0, h0, l0);
        tf32_split(v1, h1, l1);
        float4 f;
        f.x = __uint_as_float(h0); f.y = __uint_as_float(h1);
        f.z = __uint_as_float(l0); f.w = __uint_as_float(l1);
        Wfrag[i] = f;
    }

    int wrow = (warp & 3) * 16;
    int wcol = (warp >> 2) * 32;
    int ntbase = (warp >> 2) * 4;
    float bcx[4], bcy[4];
#pragma unroll
    for (int nt = 0; nt < 4; nt++) {
        int c = wcol + nt * 8 + 2 * tg;
        bcx[nt] = __ldg(&b[c]);
        bcy[nt] = __ldg(&b[c + 1]);
    }
    __syncthreads();

    for (int rb = blockIdx.x * 64; rb < NN; rb += FC_GRID * 64) {
        __syncthreads();
        for (int i = tid; i < 64 * 32; i += 256) {
            int row = i >> 5, t4 = i & 31;
            int gr = rb + row;
            float4 v = (gr < NN) ? ((const float4*)g_agg)[(size_t)gr * 32 + t4]
                                 : make_float4(0.f, 0.f, 0.f, 0.f);
            int k = t4 * 4;
            v.x = fmaxf(fmaf(v.x, scs[k + 0], shs[k + 0]), 0.f);
            v.y = fmaxf(fmaf(v.y, scs[k + 1], shs[k + 1]), 0.f);
            v.z = fmaxf(fmaf(v.z, scs[k + 2], shs[k + 2]), 0.f);
            v.w = fmaxf(fmaf(v.w, scs[k + 3], shs[k + 3]), 0.f);
            uint4 hi, lo;
            tf32_split(v.x, hi.x, lo.x);
            tf32_split(v.y, hi.y, lo.y);
            tf32_split(v.z, hi.z, lo.z);
            tf32_split(v.w, hi.w, lo.w);
            *(uint4*)(xhi + row * FC_LDX + t4 * 4) = hi;
            *(uint4*)(xlo + row * FC_LDX + t4 * 4) = lo;
        }
        __syncthreads();

        float d[4][4];
#pragma unroll
        for (int nt = 0; nt < 4; nt++) { d[nt][0]=0.f; d[nt][1]=0.f; d[nt][2]=0.f; d[nt][3]=0.f; }

#pragma unroll
        for (int ks = 0; ks < 16; ks++) {
            int k0 = ks * 8;
            unsigned int ah0 = __float_as_uint(xhi[(wrow + g) * FC_LDX + k0 + tg]);
            unsigned int ah1 = __float_as_uint(xhi[(wrow + g + 8) * FC_LDX + k0 + tg]);
            unsigned int ah2 = __float_as_uint(xhi[(wrow + g) * FC_LDX + k0 + tg + 4]);
            unsigned int ah3 = __float_as_uint(xhi[(wrow + g + 8) * FC_LDX + k0 + tg + 4]);
            unsigned int al0 = __float_as_uint(xlo[(wrow + g) * FC_LDX + k0 + tg]);
            unsigned int al1 = __float_as_uint(xlo[(wrow + g + 8) * FC_LDX + k0 + tg]);
            unsigned int al2 = __float_as_uint(xlo[(wrow + g) * FC_LDX + k0 + tg + 4]);
            unsigned int al3 = __float_as_uint(xlo[(wrow + g + 8) * FC_LDX + k0 + tg + 4]);
            const float4* wf = Wfrag + (ks * 8 + ntbase) * 32 + lane;
#pragma unroll
            for (int nt = 0; nt < 4; nt++) {
                float4 bf = wf[nt * 32];
                unsigned int bh0 = __float_as_uint(bf.x);
                unsigned int bh1 = __float_as_uint(bf.y);
                unsigned int bl0 = __float_as_uint(bf.z);
                unsigned int bl1 = __float_as_uint(bf.w);
#define MMA(A0,A1,A2,A3,B0,B1) \
                asm volatile( \
                    "mma.sync.aligned.m16n8k8.row.col.f32.tf32.tf32.f32 " \
                    "{%0,%1,%2,%3}, {%4,%5,%6,%7}, {%8,%9}, {%0,%1,%2,%3};" \
                    : "+f"(d[nt][0]), "+f"(d[nt][1]), "+f"(d[nt][2]), "+f"(d[nt][3]) \
                    : "r"(A0), "r"(A1), "r"(A2), "r"(A3), "r"(B0), "r"(B1));
                MMA(ah0, ah1, ah2, ah3, bh0, bh1)
                MMA(ah0, ah1, ah2, ah3, bl0, bl1)
                MMA(al0, al1, al2, al3, bh0, bh1)
#undef MMA
            }
        }

        int r0 = rb + wrow + g;
        int r1 = r0 + 8;
#pragma unroll
        for (int nt = 0; nt < 4; nt++) {
            int c = wcol + nt * 8 + 2 * tg;
            if (r0 < NN)
                *(float2*)(out + (size_t)r0 * OUTC + c) =
                    make_float2(d[nt][0] + bcx[nt], d[nt][1] + bcy[nt]);
            if (r1 < NN)
                *(float2*)(out + (size_t)r1 * OUTC + c) =
                    make_float2(d[nt][2] + bcx[nt], d[nt][3] + bcy[nt]);
        }
    }
}

// ---------------- launch ----------------
extern "C" void kernel_launch(void* const* d_in, const int* in_sizes, int n_in,
                              void* d_out, int out_size) {
    const float* h   = (const float*)d_in[0];
    const int*   src = (const int*)d_in[1];
    const int*   dst = (const int*)d_in[2];
    const float* w0  = (const float*)d_in[3];
    const float* b0  = (const float*)d_in[4];
    const float* w1  = (const float*)d_in[5];
    const float* b1  = (const float*)d_in[6];
    const float* w2  = (const float*)d_in[7];
    const float* b2  = (const float*)d_in[8];
    const float* g0  = (const float*)d_in[9];
    const float* bt0 = (const float*)d_in[10];
    const float* g1  = (const float*)d_in[11];
    const float* bt1 = (const float*)d_in[12];
    const float* g2  = (const float*)d_in[13];
    const float* bt2 = (const float*)d_in[14];
    const float* wfc = (const float*)d_in[15];
    const float* bfc = (const float*)d_in[16];
    float* out = (float*)d_out;

    cudaFuncSetAttribute(k_gemm_tf32, cudaFuncAttributeMaxDynamicSharedMemorySize, GT_SMEM);
    cudaFuncSetAttribute(k_gemm_l0_tf32, cudaFuncAttributeMaxDynamicSharedMemorySize, L0_SMEM);
    cudaFuncSetAttribute(k_fc_tf32, cudaFuncAttributeMaxDynamicSharedMemorySize, FC_SMEM);

    // graph prep
    k_zero_deg<<<(NN + 255) / 256, 256>>>();
    k_degrees<<<(NE / 4 + 255) / 256, 256>>>(src, dst);
    k_nodeprep_alloc<<<(NN + 255) / 256, 256>>>(h, out);
    k_fill<<<(NE / 4 + 255) / 256, 256>>>(src, dst);

    // ---- layer 0 (26 -> 128), stats -> slot 0, out fp16 ----
    k_gather26<<<(NN * 16 + 255) / 256, 256>>>();
    k_gemm_l0_tf32<<<L0_GRID, 256, L0_SMEM>>>(w0, b0);

    // ---- layers 1, 2 (128 -> 128), stats -> slots 1, 2 ----
    // layer 1 out: fp16 g_x16; layer 2 out: fp32 in-place g_agg (FC input)
    const float* Ws[2]  = {w1, w2};
    const float* bs[2]  = {b1, b2};
    const float* gs[2]  = {g0, g1};
    const float* bts[2] = {bt0, bt1};
    for (int l = 0; l < 2; l++) {
        k_prescale<<<(NN * (HID / 4) + 255) / 256, 256>>>(gs[l], bts[l], l);
        k_gather128<<<(NN * 32 + 255) / 256, 256>>>();
        k_gemm_tf32<<<GT_GRID, 256, GT_SMEM>>>(Ws[l], bs[l], l + 1, l == 1 ? 1 : 0);
    }

    // ---- final FC (128 -> 64), fp32 input from g_agg, BN2+ReLU fused ----
    k_fc_tf32<<<FC_GRID, 256, FC_SMEM>>>(wfc, bfc, g2, bt2, out);
}